// round 1
// baseline (speedup 1.0000x reference)
#include <cuda_runtime.h>
#include <math.h>
#include <stdint.h>

#define TOTAL   5120
#define DIMM    1024
#define NH      16
#define HDD     64
#define NB      4
#define MAXLEN  2048
#define NQKV    3072

// Scratch (device globals: no allocation allowed)
__device__ float g_qkv[(size_t)TOTAL * NQKV];    // 60 MB: q|k|v per token row
__device__ float g_attn[(size_t)TOTAL * DIMM];   // 20 MB: attention output

// ---------------------------------------------------------------------------
// SGEMM NT: C[M][N] = A[M][K] * B[N][K]^T   (both operands K-contiguous)
// 128x128x16 tiles, 256 threads, 8x8 per-thread micro-tile.
// Shared tiles stored k-major [16][132] so inner loop does LDS.128 loads.
// ---------------------------------------------------------------------------
__global__ void __launch_bounds__(256, 2) sgemm_nt(
    const float* __restrict__ A, const float* __restrict__ Bw,
    float* __restrict__ C, int M, int N, int K)
{
    __shared__ float As[16][132];
    __shared__ float Bs[16][132];
    const int tid = threadIdx.x;
    const int tx = tid & 15, ty = tid >> 4;
    const int bm = blockIdx.y * 128, bn = blockIdx.x * 128;

    float acc[8][8];
#pragma unroll
    for (int i = 0; i < 8; i++)
#pragma unroll
        for (int j = 0; j < 8; j++) acc[i][j] = 0.f;

    for (int k0 = 0; k0 < K; k0 += 16) {
#pragma unroll
        for (int t = 0; t < 2; t++) {
            int f4  = tid * 2 + t;        // 0..511 float4s per operand tile
            int row = f4 >> 2;            // 0..127
            int kk  = (f4 & 3) << 2;      // 0,4,8,12
            float4 va = *(const float4*)&A [(size_t)(bm + row) * K + k0 + kk];
            As[kk+0][row] = va.x; As[kk+1][row] = va.y;
            As[kk+2][row] = va.z; As[kk+3][row] = va.w;
            float4 vb = *(const float4*)&Bw[(size_t)(bn + row) * K + k0 + kk];
            Bs[kk+0][row] = vb.x; Bs[kk+1][row] = vb.y;
            Bs[kk+2][row] = vb.z; Bs[kk+3][row] = vb.w;
        }
        __syncthreads();
#pragma unroll
        for (int kk = 0; kk < 16; kk++) {
            float a[8], b[8];
            *(float4*)&a[0] = *(const float4*)&As[kk][ty * 8 + 0];
            *(float4*)&a[4] = *(const float4*)&As[kk][ty * 8 + 4];
            *(float4*)&b[0] = *(const float4*)&Bs[kk][tx * 8 + 0];
            *(float4*)&b[4] = *(const float4*)&Bs[kk][tx * 8 + 4];
#pragma unroll
            for (int i = 0; i < 8; i++)
#pragma unroll
                for (int j = 0; j < 8; j++)
                    acc[i][j] = fmaf(a[i], b[j], acc[i][j]);
        }
        __syncthreads();
    }

#pragma unroll
    for (int i = 0; i < 8; i++) {
        float* cp = &C[(size_t)(bm + ty * 8 + i) * N + bn + tx * 8];
        *(float4*)&cp[0] = make_float4(acc[i][0], acc[i][1], acc[i][2], acc[i][3]);
        *(float4*)&cp[4] = make_float4(acc[i][4], acc[i][5], acc[i][6], acc[i][7]);
    }
}

// ---------------------------------------------------------------------------
// RoPE in-place on the q and k sections of g_qkv.
// One thread per (row, section, head, pair j). Position from cu_seqlens.
// ---------------------------------------------------------------------------
__global__ void __launch_bounds__(256) rope_kernel(const int* __restrict__ cu)
{
    int t = blockIdx.x * 256 + threadIdx.x;      // TOTAL*2*16*32 threads
    int j  = t & 31;
    int hh = (t >> 5) & 15;
    int s  = (t >> 9) & 1;
    int r  = t >> 10;
    if (r >= TOTAL) return;

    int b = 0;
#pragma unroll
    for (int i = 1; i < NB; i++) if (r >= cu[i]) b = i;
    int pos = r - cu[b];

    // inv_freq = 10000^(-j/32) = 2^(-j/32 * log2(10000))
    float inv = exp2f(-(float)j * (13.287712379549449f / 32.0f));
    float fr  = (float)pos * inv;
    float c, sn;
    sincosf(fr, &sn, &c);

    float* base = g_qkv + (size_t)r * NQKV + s * DIMM + hh * HDD;
    float x1 = base[j], x2 = base[j + 32];
    base[j]      = x1 * c - x2 * sn;
    base[j + 32] = x2 * c + x1 * sn;
}

// ---------------------------------------------------------------------------
// Flash-style attention over REAL keys only; zero-score padded keys folded
// analytically into the softmax denominator (n_pad * exp(-m), m >= 0).
// Block: 64 queries of one (batch,head); 256 threads, 4x4 per thread.
// ---------------------------------------------------------------------------
__global__ void __launch_bounds__(256) attn_kernel(const int* __restrict__ cu)
{
    extern __shared__ float sm[];
    float* Qs  = sm;                 // [64][65]
    float* KPs = sm + 64 * 65;       // [64][65]  K tile, reused for P tile
    float* Vs  = sm + 2 * 64 * 65;   // [64][64]

    const int tid = threadIdx.x;
    const int tx = tid & 15, ty = tid >> 4;
    const int h  = blockIdx.y;
    const int qt = blockIdx.x * 64;  // global query-row start

    int b = 0;
#pragma unroll
    for (int i = 1; i < NB; i++) if (qt >= cu[i]) b = i;
    const int base = cu[b];
    const int L    = cu[b + 1] - base;

    // load Q tile
#pragma unroll
    for (int i = 0; i < 16; i++) {
        int idx = tid + 256 * i;
        int r = idx >> 6, d = idx & 63;
        Qs[r * 65 + d] = g_qkv[(size_t)(qt + r) * NQKV + h * HDD + d];
    }

    float m_[4], l_[4], o_[4][4];
#pragma unroll
    for (int i = 0; i < 4; i++) {
        m_[i] = -1e30f; l_[i] = 0.f;
#pragma unroll
        for (int j = 0; j < 4; j++) o_[i][j] = 0.f;
    }

    const int nkt = L >> 6;
    for (int kt = 0; kt < nkt; kt++) {
        __syncthreads();
        const size_t krow0 = (size_t)(base + kt * 64);
#pragma unroll
        for (int i = 0; i < 16; i++) {
            int idx = tid + 256 * i;
            int r = idx >> 6, d = idx & 63;
            const float* src = &g_qkv[(krow0 + r) * NQKV + h * HDD + d];
            KPs[r * 65 + d] = src[DIMM];
            Vs [r * 64 + d] = src[2 * DIMM];
        }
        __syncthreads();

        // S = Q K^T (64x64), each thread 4x4
        float s[4][4];
#pragma unroll
        for (int i = 0; i < 4; i++)
#pragma unroll
            for (int j = 0; j < 4; j++) s[i][j] = 0.f;

        for (int kk = 0; kk < 64; kk++) {
            float qv[4], kv[4];
#pragma unroll
            for (int i = 0; i < 4; i++) qv[i] = Qs[(ty * 4 + i) * 65 + kk];
#pragma unroll
            for (int j = 0; j < 4; j++) kv[j] = KPs[(tx * 4 + j) * 65 + kk];
#pragma unroll
            for (int i = 0; i < 4; i++)
#pragma unroll
                for (int j = 0; j < 4; j++)
                    s[i][j] = fmaf(qv[i], kv[j], s[i][j]);
        }
        __syncthreads();   // all done reading K before overwriting with P

        // online softmax; write P into KPs
#pragma unroll
        for (int i = 0; i < 4; i++) {
#pragma unroll
            for (int j = 0; j < 4; j++) s[i][j] *= 0.125f;
            float rm = fmaxf(fmaxf(s[i][0], s[i][1]), fmaxf(s[i][2], s[i][3]));
#pragma unroll
            for (int off = 1; off < 16; off <<= 1)
                rm = fmaxf(rm, __shfl_xor_sync(0xffffffffu, rm, off));
            float mn = fmaxf(m_[i], rm);
            float f  = __expf(m_[i] - mn);
            float rs = 0.f;
#pragma unroll
            for (int j = 0; j < 4; j++) { s[i][j] = __expf(s[i][j] - mn); rs += s[i][j]; }
#pragma unroll
            for (int off = 1; off < 16; off <<= 1)
                rs += __shfl_xor_sync(0xffffffffu, rs, off);
            l_[i] = l_[i] * f + rs;
            m_[i] = mn;
#pragma unroll
            for (int j = 0; j < 4; j++) o_[i][j] *= f;
#pragma unroll
            for (int j = 0; j < 4; j++) KPs[(ty * 4 + i) * 65 + tx * 4 + j] = s[i][j];
        }
        __syncthreads();

        // O += P V
        for (int kr = 0; kr < 64; kr++) {
            float pv[4];
#pragma unroll
            for (int i = 0; i < 4; i++) pv[i] = KPs[(ty * 4 + i) * 65 + kr];
            float4 vv = *(const float4*)&Vs[kr * 64 + tx * 4];
#pragma unroll
            for (int i = 0; i < 4; i++) {
                o_[i][0] = fmaf(pv[i], vv.x, o_[i][0]);
                o_[i][1] = fmaf(pv[i], vv.y, o_[i][1]);
                o_[i][2] = fmaf(pv[i], vv.z, o_[i][2]);
                o_[i][3] = fmaf(pv[i], vv.w, o_[i][3]);
            }
        }
    }

    // fold padded keys (score 0, v 0) into the denominator; normalize & store
    const float npad = (float)(MAXLEN - L);
#pragma unroll
    for (int i = 0; i < 4; i++) {
        float mf = m_[i];
        if (npad > 0.f) mf = fmaxf(mf, 0.f);
        float scale = __expf(m_[i] - mf);
        float denom = l_[i] * scale + npad * __expf(-mf);
        float w = scale / denom;
        float* dst = &g_attn[(size_t)(qt + ty * 4 + i) * DIMM + h * HDD + tx * 4];
#pragma unroll
        for (int j = 0; j < 4; j++) dst[j] = o_[i][j] * w;
    }
}

// ---------------------------------------------------------------------------
extern "C" void kernel_launch(void* const* d_in, const int* in_sizes, int n_in,
                              void* d_out, int out_size)
{
    const float* hs   = (const float*)d_in[0];   // [5120,1024]
    const float* wqkv = (const float*)d_in[1];   // [3072,1024]
    const float* wo   = (const float*)d_in[2];   // [1024,1024]
    const int*   cu   = (const int*)  d_in[3];   // [5] cu_seqlens
    float* out = (float*)d_out;                  // [5120,1024]

    float *qkv_p = nullptr, *attn_p = nullptr;
    cudaGetSymbolAddress((void**)&qkv_p,  g_qkv);
    cudaGetSymbolAddress((void**)&attn_p, g_attn);
    cudaFuncSetAttribute(attn_kernel,
                         cudaFuncAttributeMaxDynamicSharedMemorySize, 49664);

    // 1) QKV projection
    sgemm_nt<<<dim3(NQKV / 128, TOTAL / 128), 256>>>(hs, wqkv, qkv_p,
                                                     TOTAL, NQKV, DIMM);
    // 2) RoPE on q,k (in place)
    rope_kernel<<<(TOTAL * 2 * NH * 32) / 256, 256>>>(cu);
    // 3) attention (flash over real keys + analytic padding term)
    attn_kernel<<<dim3(TOTAL / 64, NH), 256, 49664>>>(cu);
    // 4) output projection
    sgemm_nt<<<dim3(DIMM / 128, TOTAL / 128), 256>>>(attn_p, wo, out,
                                                     TOTAL, DIMM, DIMM);
}

// round 2
// speedup vs baseline: 1.4305x; 1.4305x over previous
#include <cuda_runtime.h>
#include <math.h>
#include <stdint.h>

#define TOTAL   5120
#define DIMM    1024
#define NH      16
#define HDD     64
#define NB      4
#define MAXLEN  2048
#define NQKV    3072

// Scratch (device globals: no allocation allowed)
__device__ float g_qkv[(size_t)TOTAL * NQKV];    // 60 MB: q|k|v per token row
__device__ float g_attn[(size_t)TOTAL * DIMM];   // 20 MB: attention output

__device__ __forceinline__ unsigned tf32r(float x) {
    unsigned u;
    asm("cvt.rna.tf32.f32 %0, %1;" : "=r"(u) : "f"(x));
    return u;
}

// ---------------------------------------------------------------------------
// TF32 tensor-core GEMM NT: C[M][N] = A[M][K] * B[N][K]^T
// 128x128x32 tiles, 256 threads (8 warps, 2x4), warp tile 64x32,
// mma.sync.m16n8k8 tf32. Shared layout: row stride 36, k-octets interleaved
// (pos = 2*(k&3) + (k>>2)) so each fragment pair (k=t, k=t+4) is one LDS.64.
// ---------------------------------------------------------------------------
__global__ void __launch_bounds__(256, 2) tf32_gemm_nt(
    const float* __restrict__ A, const float* __restrict__ Bw,
    float* __restrict__ C, int M, int N, int K)
{
    __shared__ unsigned As[128 * 36];
    __shared__ unsigned Bs[128 * 36];

    const int tid  = threadIdx.x;
    const int lane = tid & 31, w = tid >> 5;
    const int g = lane >> 2, t = lane & 3;
    const int wm = w >> 2, wn = w & 3;          // 2 x 4 warp grid
    const int bm = blockIdx.y * 128, bn = blockIdx.x * 128;

    float acc[4][4][4];
#pragma unroll
    for (int mt = 0; mt < 4; mt++)
#pragma unroll
        for (int nt = 0; nt < 4; nt++)
#pragma unroll
            for (int r = 0; r < 4; r++) acc[mt][nt][r] = 0.f;

    for (int k0 = 0; k0 < K; k0 += 32) {
        // ---- stage 128x32 A and B tiles (convert to tf32, k-interleave) ----
#pragma unroll
        for (int it = 0; it < 4; it++) {
            int f4  = tid + 256 * it;
            int row = f4 >> 3;            // 0..127
            int c   = f4 & 7;             // float4 index within row
            int base = row * 36 + (c >> 1) * 8 + (c & 1);
            float4 va = *(const float4*)&A [(size_t)(bm + row) * K + k0 + c * 4];
            As[base + 0] = tf32r(va.x); As[base + 2] = tf32r(va.y);
            As[base + 4] = tf32r(va.z); As[base + 6] = tf32r(va.w);
            float4 vb = *(const float4*)&Bw[(size_t)(bn + row) * K + k0 + c * 4];
            Bs[base + 0] = tf32r(vb.x); Bs[base + 2] = tf32r(vb.y);
            Bs[base + 4] = tf32r(vb.z); Bs[base + 6] = tf32r(vb.w);
        }
        __syncthreads();

        // ---- compute: 4 k-octets, 4x4 mma tiles per warp ----
#pragma unroll
        for (int o = 0; o < 4; o++) {
            unsigned a[4][4], b[4][2];
#pragma unroll
            for (int mt = 0; mt < 4; mt++) {
                int r0 = (wm * 64 + mt * 16 + g) * 36 + o * 8 + 2 * t;
                uint2 lo = *(const uint2*)&As[r0];
                uint2 hi = *(const uint2*)&As[r0 + 8 * 36];
                a[mt][0] = lo.x; a[mt][2] = lo.y;
                a[mt][1] = hi.x; a[mt][3] = hi.y;
            }
#pragma unroll
            for (int nt = 0; nt < 4; nt++) {
                uint2 bb = *(const uint2*)&Bs[(wn * 32 + nt * 8 + g) * 36 + o * 8 + 2 * t];
                b[nt][0] = bb.x; b[nt][1] = bb.y;
            }
#pragma unroll
            for (int mt = 0; mt < 4; mt++)
#pragma unroll
                for (int nt = 0; nt < 4; nt++) {
                    asm volatile(
                        "mma.sync.aligned.m16n8k8.row.col.f32.tf32.tf32.f32 "
                        "{%0,%1,%2,%3}, {%4,%5,%6,%7}, {%8,%9}, {%0,%1,%2,%3};"
                        : "+f"(acc[mt][nt][0]), "+f"(acc[mt][nt][1]),
                          "+f"(acc[mt][nt][2]), "+f"(acc[mt][nt][3])
                        : "r"(a[mt][0]), "r"(a[mt][1]), "r"(a[mt][2]), "r"(a[mt][3]),
                          "r"(b[nt][0]), "r"(b[nt][1]));
                }
        }
        __syncthreads();
    }

    // ---- epilogue ----
#pragma unroll
    for (int mt = 0; mt < 4; mt++) {
        int r = bm + wm * 64 + mt * 16 + g;
#pragma unroll
        for (int nt = 0; nt < 4; nt++) {
            int cn = bn + wn * 32 + nt * 8 + 2 * t;
            *(float2*)&C[(size_t)r * N + cn]       = make_float2(acc[mt][nt][0], acc[mt][nt][1]);
            *(float2*)&C[(size_t)(r + 8) * N + cn] = make_float2(acc[mt][nt][2], acc[mt][nt][3]);
        }
    }
}

// ---------------------------------------------------------------------------
// RoPE in-place on the q and k sections of g_qkv.
// ---------------------------------------------------------------------------
__global__ void __launch_bounds__(256) rope_kernel(const int* __restrict__ cu)
{
    int t = blockIdx.x * 256 + threadIdx.x;      // TOTAL*2*16*32 threads
    int j  = t & 31;
    int hh = (t >> 5) & 15;
    int s  = (t >> 9) & 1;
    int r  = t >> 10;
    if (r >= TOTAL) return;

    int b = 0;
#pragma unroll
    for (int i = 1; i < NB; i++) if (r >= cu[i]) b = i;
    int pos = r - cu[b];

    float inv = exp2f(-(float)j * (13.287712379549449f / 32.0f));
    float fr  = (float)pos * inv;
    float c, sn;
    sincosf(fr, &sn, &c);

    float* base = g_qkv + (size_t)r * NQKV + s * DIMM + hh * HDD;
    float x1 = base[j], x2 = base[j + 32];
    base[j]      = x1 * c - x2 * sn;
    base[j + 32] = x2 * c + x1 * sn;
}

// ---------------------------------------------------------------------------
// Flash-style attention over REAL keys only; zero-score padded keys folded
// analytically into the softmax denominator (n_pad * exp(-m), m >= 0).
// ---------------------------------------------------------------------------
__global__ void __launch_bounds__(256) attn_kernel(const int* __restrict__ cu)
{
    extern __shared__ float sm[];
    float* Qs  = sm;                 // [64][65]
    float* KPs = sm + 64 * 65;       // [64][65]  K tile, reused for P tile
    float* Vs  = sm + 2 * 64 * 65;   // [64][64]

    const int tid = threadIdx.x;
    const int tx = tid & 15, ty = tid >> 4;
    const int h  = blockIdx.y;
    const int qt = blockIdx.x * 64;

    int b = 0;
#pragma unroll
    for (int i = 1; i < NB; i++) if (qt >= cu[i]) b = i;
    const int base = cu[b];
    const int L    = cu[b + 1] - base;

#pragma unroll
    for (int i = 0; i < 16; i++) {
        int idx = tid + 256 * i;
        int r = idx >> 6, d = idx & 63;
        Qs[r * 65 + d] = g_qkv[(size_t)(qt + r) * NQKV + h * HDD + d];
    }

    float m_[4], l_[4], o_[4][4];
#pragma unroll
    for (int i = 0; i < 4; i++) {
        m_[i] = -1e30f; l_[i] = 0.f;
#pragma unroll
        for (int j = 0; j < 4; j++) o_[i][j] = 0.f;
    }

    const int nkt = L >> 6;
    for (int kt = 0; kt < nkt; kt++) {
        __syncthreads();
        const size_t krow0 = (size_t)(base + kt * 64);
#pragma unroll
        for (int i = 0; i < 16; i++) {
            int idx = tid + 256 * i;
            int r = idx >> 6, d = idx & 63;
            const float* src = &g_qkv[(krow0 + r) * NQKV + h * HDD + d];
            KPs[r * 65 + d] = src[DIMM];
            Vs [r * 64 + d] = src[2 * DIMM];
        }
        __syncthreads();

        float s[4][4];
#pragma unroll
        for (int i = 0; i < 4; i++)
#pragma unroll
            for (int j = 0; j < 4; j++) s[i][j] = 0.f;

        for (int kk = 0; kk < 64; kk++) {
            float qv[4], kv[4];
#pragma unroll
            for (int i = 0; i < 4; i++) qv[i] = Qs[(ty * 4 + i) * 65 + kk];
#pragma unroll
            for (int j = 0; j < 4; j++) kv[j] = KPs[(tx * 4 + j) * 65 + kk];
#pragma unroll
            for (int i = 0; i < 4; i++)
#pragma unroll
                for (int j = 0; j < 4; j++)
                    s[i][j] = fmaf(qv[i], kv[j], s[i][j]);
        }
        __syncthreads();

#pragma unroll
        for (int i = 0; i < 4; i++) {
#pragma unroll
            for (int j = 0; j < 4; j++) s[i][j] *= 0.125f;
            float rm = fmaxf(fmaxf(s[i][0], s[i][1]), fmaxf(s[i][2], s[i][3]));
#pragma unroll
            for (int off = 1; off < 16; off <<= 1)
                rm = fmaxf(rm, __shfl_xor_sync(0xffffffffu, rm, off));
            float mn = fmaxf(m_[i], rm);
            float f  = __expf(m_[i] - mn);
            float rs = 0.f;
#pragma unroll
            for (int j = 0; j < 4; j++) { s[i][j] = __expf(s[i][j] - mn); rs += s[i][j]; }
#pragma unroll
            for (int off = 1; off < 16; off <<= 1)
                rs += __shfl_xor_sync(0xffffffffu, rs, off);
            l_[i] = l_[i] * f + rs;
            m_[i] = mn;
#pragma unroll
            for (int j = 0; j < 4; j++) o_[i][j] *= f;
#pragma unroll
            for (int j = 0; j < 4; j++) KPs[(ty * 4 + i) * 65 + tx * 4 + j] = s[i][j];
        }
        __syncthreads();

        for (int kr = 0; kr < 64; kr++) {
            float pv[4];
#pragma unroll
            for (int i = 0; i < 4; i++) pv[i] = KPs[(ty * 4 + i) * 65 + kr];
            float4 vv = *(const float4*)&Vs[kr * 64 + tx * 4];
#pragma unroll
            for (int i = 0; i < 4; i++) {
                o_[i][0] = fmaf(pv[i], vv.x, o_[i][0]);
                o_[i][1] = fmaf(pv[i], vv.y, o_[i][1]);
                o_[i][2] = fmaf(pv[i], vv.z, o_[i][2]);
                o_[i][3] = fmaf(pv[i], vv.w, o_[i][3]);
            }
        }
    }

    const float npad = (float)(MAXLEN - L);
#pragma unroll
    for (int i = 0; i < 4; i++) {
        float mf = m_[i];
        if (npad > 0.f) mf = fmaxf(mf, 0.f);
        float scale = __expf(m_[i] - mf);
        float denom = l_[i] * scale + npad * __expf(-mf);
        float w2 = scale / denom;
        float* dst = &g_attn[(size_t)(qt + ty * 4 + i) * DIMM + h * HDD + tx * 4];
#pragma unroll
        for (int j = 0; j < 4; j++) dst[j] = o_[i][j] * w2;
    }
}

// ---------------------------------------------------------------------------
extern "C" void kernel_launch(void* const* d_in, const int* in_sizes, int n_in,
                              void* d_out, int out_size)
{
    const float* hs   = (const float*)d_in[0];   // [5120,1024]
    const float* wqkv = (const float*)d_in[1];   // [3072,1024]
    const float* wo   = (const float*)d_in[2];   // [1024,1024]
    const int*   cu   = (const int*)  d_in[3];   // [5] cu_seqlens
    float* out = (float*)d_out;                  // [5120,1024]

    float *qkv_p = nullptr, *attn_p = nullptr;
    cudaGetSymbolAddress((void**)&qkv_p,  g_qkv);
    cudaGetSymbolAddress((void**)&attn_p, g_attn);
    cudaFuncSetAttribute(attn_kernel,
                         cudaFuncAttributeMaxDynamicSharedMemorySize, 49664);

    // 1) QKV projection (tf32 tensor cores)
    tf32_gemm_nt<<<dim3(NQKV / 128, TOTAL / 128), 256>>>(hs, wqkv, qkv_p,
                                                         TOTAL, NQKV, DIMM);
    // 2) RoPE on q,k (in place)
    rope_kernel<<<(TOTAL * 2 * NH * 32) / 256, 256>>>(cu);
    // 3) attention (flash over real keys + analytic padding term)
    attn_kernel<<<dim3(TOTAL / 64, NH), 256, 49664>>>(cu);
    // 4) output projection (tf32 tensor cores)
    tf32_gemm_nt<<<dim3(DIMM / 128, TOTAL / 128), 256>>>(attn_p, wo, out,
                                                         TOTAL, DIMM, DIMM);
}

// round 3
// speedup vs baseline: 2.9426x; 2.0571x over previous
#include <cuda_runtime.h>
#include <math.h>
#include <stdint.h>

#define TOTAL   5120
#define DIMM    1024
#define NH      16
#define HDD     64
#define NB      4
#define MAXLEN  2048
#define NQKV    3072

// Scratch (device globals: no allocation allowed)
__device__ float g_qkv[(size_t)TOTAL * NQKV];    // q|k|v per token row
__device__ float g_attn[(size_t)TOTAL * DIMM];   // attention output

__device__ __forceinline__ unsigned tf32r(float x) {
    unsigned u;
    asm("cvt.rna.tf32.f32 %0, %1;" : "=r"(u) : "f"(x));
    return u;
}

#define MMA_TF32(acc, a0,a1,a2,a3, b0,b1)                                     \
    asm volatile("mma.sync.aligned.m16n8k8.row.col.f32.tf32.tf32.f32 "        \
                 "{%0,%1,%2,%3}, {%4,%5,%6,%7}, {%8,%9}, {%0,%1,%2,%3};"      \
                 : "+f"((acc)[0]), "+f"((acc)[1]), "+f"((acc)[2]), "+f"((acc)[3]) \
                 : "r"(a0), "r"(a1), "r"(a2), "r"(a3), "r"(b0), "r"(b1))

extern __shared__ float dynsm[];

// ---------------------------------------------------------------------------
// TF32 GEMM NT: C[M][N] = A[M][K]*B[N][K]^T. 128x128x32 tiles, 8 warps.
// cp.async double-buffered; chunk-XOR swizzled smem (conflict-free LDS.32);
// cvt.rna at fragment load (raw fp32 staged).
// ---------------------------------------------------------------------------
__global__ void __launch_bounds__(256, 2) tf32_gemm_nt(
    const float* __restrict__ A, const float* __restrict__ Bw,
    float* __restrict__ C, int M, int N, int K)
{
    float* As = dynsm;            // [2][128*32]
    float* Bs = dynsm + 8192;     // [2][128*32]

    const int tid  = threadIdx.x;
    const int lane = tid & 31, w = tid >> 5;
    const int g = lane >> 2, t = lane & 3;
    const int wm = w >> 2, wn = w & 3;
    const int bm = blockIdx.y * 128, bn = blockIdx.x * 128;

    float acc[4][4][4] = {};

    const unsigned sA0 = (unsigned)__cvta_generic_to_shared(As);
    const unsigned sB0 = (unsigned)__cvta_generic_to_shared(Bs);

#define GEMM_STAGE(buf, k0)                                                   \
    {                                                                         \
        unsigned sa = sA0 + (buf) * 16384, sb = sB0 + (buf) * 16384;          \
        _Pragma("unroll")                                                     \
        for (int it = 0; it < 4; it++) {                                      \
            int id = tid + 256 * it;                                          \
            int row = id >> 3, c = id & 7;                                    \
            unsigned off = (unsigned)(row * 32 + ((c ^ (row & 7)) << 2)) * 4; \
            const float* pa = &A [(size_t)(bm + row) * K + (k0) + c * 4];     \
            const float* pb = &Bw[(size_t)(bn + row) * K + (k0) + c * 4];     \
            asm volatile("cp.async.ca.shared.global [%0],[%1],16;\n"          \
                         :: "r"(sa + off), "l"(pa));                          \
            asm volatile("cp.async.ca.shared.global [%0],[%1],16;\n"          \
                         :: "r"(sb + off), "l"(pb));                          \
        }                                                                     \
        asm volatile("cp.async.commit_group;\n");                             \
    }

    GEMM_STAGE(0, 0);
    int buf = 0;
    for (int k0 = 0; k0 < K; k0 += 32) {
        asm volatile("cp.async.wait_group 0;\n");
        __syncthreads();
        if (k0 + 32 < K) GEMM_STAGE(buf ^ 1, k0 + 32);

        const float* Ab = As + buf * 4096;
        const float* Bb = Bs + buf * 4096;
#pragma unroll
        for (int o = 0; o < 4; o++) {
            const int c0 = ((2 * o) ^ g) << 2, c1 = ((2 * o + 1) ^ g) << 2;
            unsigned a[4][4], b[4][2];
#pragma unroll
            for (int mt = 0; mt < 4; mt++) {
                int r0 = wm * 64 + mt * 16 + g;
                a[mt][0] = tf32r(Ab[ r0      * 32 + c0 + t]);
                a[mt][2] = tf32r(Ab[ r0      * 32 + c1 + t]);
                a[mt][1] = tf32r(Ab[(r0 + 8) * 32 + c0 + t]);
                a[mt][3] = tf32r(Ab[(r0 + 8) * 32 + c1 + t]);
            }
#pragma unroll
            for (int nt = 0; nt < 4; nt++) {
                int r0 = wn * 32 + nt * 8 + g;
                b[nt][0] = tf32r(Bb[r0 * 32 + c0 + t]);
                b[nt][1] = tf32r(Bb[r0 * 32 + c1 + t]);
            }
#pragma unroll
            for (int mt = 0; mt < 4; mt++)
#pragma unroll
                for (int nt = 0; nt < 4; nt++)
                    MMA_TF32(acc[mt][nt], a[mt][0], a[mt][1], a[mt][2], a[mt][3],
                             b[nt][0], b[nt][1]);
        }
        buf ^= 1;
    }

#pragma unroll
    for (int mt = 0; mt < 4; mt++) {
        int r = bm + wm * 64 + mt * 16 + g;
#pragma unroll
        for (int nt = 0; nt < 4; nt++) {
            int cn = bn + wn * 32 + nt * 8 + 2 * t;
            *(float2*)&C[(size_t)r * N + cn]       = make_float2(acc[mt][nt][0], acc[mt][nt][1]);
            *(float2*)&C[(size_t)(r + 8) * N + cn] = make_float2(acc[mt][nt][2], acc[mt][nt][3]);
        }
    }
}

// ---------------------------------------------------------------------------
// RoPE in-place on the q and k sections of g_qkv.
// ---------------------------------------------------------------------------
__global__ void __launch_bounds__(256) rope_kernel(const int* __restrict__ cu)
{
    int tt = blockIdx.x * 256 + threadIdx.x;
    int j  = tt & 31;
    int hh = (tt >> 5) & 15;
    int s  = (tt >> 9) & 1;
    int r  = tt >> 10;
    if (r >= TOTAL) return;

    int b = 0;
#pragma unroll
    for (int i = 1; i < NB; i++) if (r >= cu[i]) b = i;
    int pos = r - cu[b];

    float inv = exp2f(-(float)j * (13.287712379549449f / 32.0f));
    float fr  = (float)pos * inv;
    float c, sn;
    sincosf(fr, &sn, &c);

    float* base = g_qkv + (size_t)r * NQKV + s * DIMM + hh * HDD;
    float x1 = base[j], x2 = base[j + 32];
    base[j]      = x1 * c - x2 * sn;
    base[j + 32] = x2 * c + x1 * sn;
}

// ---------------------------------------------------------------------------
// Tensor-core flash attention (tf32). Block = 128 q-rows x 1 head, 8 warps
// (warp = 16 q-rows). S=QK^T via mma, online softmax in fragment layout,
// P staged through warp-local swizzled smem into the PV mma.
// Padded keys folded analytically into the softmax denominator.
// ---------------------------------------------------------------------------
__global__ void __launch_bounds__(256, 2) attn_kernel(const int* __restrict__ cu)
{
    float* Qs = dynsm;             // 128*64 (tf32 bits, pre-scaled by 1/8)
    float* Ks = dynsm + 8192;      // 64*64  (tf32 bits)
    float* Vs = dynsm + 12288;     // 64*64  (tf32 bits)
    float* Ps = dynsm + 16384;     // 128*64 (tf32 bits)

    const int tid  = threadIdx.x;
    const int lane = tid & 31, w = tid >> 5;
    const int g = lane >> 2, t = lane & 3;
    const int h  = blockIdx.y;
    const int qt = blockIdx.x * 128;

    int b = 0;
#pragma unroll
    for (int i = 1; i < NB; i++) if (qt >= cu[i]) b = i;
    const int base = cu[b];
    const int L    = cu[b + 1] - base;

    // stage Q (scale by 1/8, round to tf32)
#pragma unroll
    for (int it = 0; it < 8; it++) {
        int id = tid + 256 * it;            // 2048 chunks
        int row = id >> 4, c = id & 15;
        float4 v = *(const float4*)&g_qkv[(size_t)(qt + row) * NQKV + h * HDD + c * 4];
        float* d = &Qs[row * 64 + ((c ^ (row & 7)) << 2)];
        d[0] = __uint_as_float(tf32r(v.x * 0.125f));
        d[1] = __uint_as_float(tf32r(v.y * 0.125f));
        d[2] = __uint_as_float(tf32r(v.z * 0.125f));
        d[3] = __uint_as_float(tf32r(v.w * 0.125f));
    }

    const int r0l = w * 16 + g;             // warp-local A rows: r0l, r0l+8
    float m0 = -1e30f, m1 = -1e30f, l0 = 0.f, l1 = 0.f;
    float o_[8][4] = {};

    const int nkt = L >> 6;
    for (int kt = 0; kt < nkt; kt++) {
        __syncthreads();                    // prev tile's reads done
        const size_t kr0 = (size_t)(base + kt * 64);
#pragma unroll
        for (int it = 0; it < 4; it++) {
            int id = tid + 256 * it;        // 1024 chunks
            int row = id >> 4, c = id & 15;
            const float* src = &g_qkv[(kr0 + row) * NQKV + h * HDD + c * 4];
            float4 kv = *(const float4*)&src[DIMM];
            float4 vv = *(const float4*)&src[2 * DIMM];
            float* dk = &Ks[row * 64 + ((c ^ (row & 7)) << 2)];
            dk[0] = __uint_as_float(tf32r(kv.x));
            dk[1] = __uint_as_float(tf32r(kv.y));
            dk[2] = __uint_as_float(tf32r(kv.z));
            dk[3] = __uint_as_float(tf32r(kv.w));
            float* dv = &Vs[row * 64 + ((c ^ (row & 7)) << 2)];
            dv[0] = __uint_as_float(tf32r(vv.x));
            dv[1] = __uint_as_float(tf32r(vv.y));
            dv[2] = __uint_as_float(tf32r(vv.z));
            dv[3] = __uint_as_float(tf32r(vv.w));
        }
        __syncthreads();

        // ---- S = Q K^T : 8 n-tiles (keys) x 8 k-octets (dims) ----
        float s[8][4] = {};
#pragma unroll
        for (int o = 0; o < 8; o++) {
            const int c0 = ((2 * o) ^ g) << 2, c1 = ((2 * o + 1) ^ g) << 2;
            unsigned a0 = __float_as_uint(Qs[ r0l      * 64 + c0 + t]);
            unsigned a2 = __float_as_uint(Qs[ r0l      * 64 + c1 + t]);
            unsigned a1 = __float_as_uint(Qs[(r0l + 8) * 64 + c0 + t]);
            unsigned a3 = __float_as_uint(Qs[(r0l + 8) * 64 + c1 + t]);
#pragma unroll
            for (int j = 0; j < 8; j++) {
                int rb = j * 8 + g;
                unsigned b0 = __float_as_uint(Ks[rb * 64 + c0 + t]);
                unsigned b1 = __float_as_uint(Ks[rb * 64 + c1 + t]);
                MMA_TF32(s[j], a0, a1, a2, a3, b0, b1);
            }
        }

        // ---- online softmax (rows r0l and r0l+8) ----
        float rm0 = -1e30f, rm1 = -1e30f;
#pragma unroll
        for (int j = 0; j < 8; j++) {
            rm0 = fmaxf(rm0, fmaxf(s[j][0], s[j][1]));
            rm1 = fmaxf(rm1, fmaxf(s[j][2], s[j][3]));
        }
#pragma unroll
        for (int off = 1; off < 4; off <<= 1) {
            rm0 = fmaxf(rm0, __shfl_xor_sync(0xffffffffu, rm0, off));
            rm1 = fmaxf(rm1, __shfl_xor_sync(0xffffffffu, rm1, off));
        }
        float mn0 = fmaxf(m0, rm0), mn1 = fmaxf(m1, rm1);
        float f0 = __expf(m0 - mn0), f1 = __expf(m1 - mn1);
        float rs0 = 0.f, rs1 = 0.f;
#pragma unroll
        for (int j = 0; j < 8; j++) {
            s[j][0] = __expf(s[j][0] - mn0); rs0 += s[j][0];
            s[j][1] = __expf(s[j][1] - mn0); rs0 += s[j][1];
            s[j][2] = __expf(s[j][2] - mn1); rs1 += s[j][2];
            s[j][3] = __expf(s[j][3] - mn1); rs1 += s[j][3];
        }
#pragma unroll
        for (int off = 1; off < 4; off <<= 1) {
            rs0 += __shfl_xor_sync(0xffffffffu, rs0, off);
            rs1 += __shfl_xor_sync(0xffffffffu, rs1, off);
        }
        l0 = l0 * f0 + rs0;  m0 = mn0;
        l1 = l1 * f1 + rs1;  m1 = mn1;
#pragma unroll
        for (int j = 0; j < 8; j++) {
            o_[j][0] *= f0; o_[j][1] *= f0;
            o_[j][2] *= f1; o_[j][3] *= f1;
        }

        // ---- P -> warp-local swizzled smem (tf32) ----
#pragma unroll
        for (int j = 0; j < 8; j++) {
            int ch = 2 * j + (t >> 1);             // key-col chunk
            int wd = 2 * (t & 1);                  // word within chunk (even)
            float* p0 = &Ps[ r0l      * 64 + ((ch ^ g) << 2) + wd];
            p0[0] = __uint_as_float(tf32r(s[j][0]));
            p0[1] = __uint_as_float(tf32r(s[j][1]));
            float* p1 = &Ps[(r0l + 8) * 64 + ((ch ^ g) << 2) + wd];
            p1[0] = __uint_as_float(tf32r(s[j][2]));
            p1[1] = __uint_as_float(tf32r(s[j][3]));
        }
        __syncwarp();

        // ---- O += P V : k-octets over keys, n-tiles over dims ----
#pragma unroll
        for (int o = 0; o < 8; o++) {
            const int c0 = ((2 * o) ^ g) << 2, c1 = ((2 * o + 1) ^ g) << 2;
            unsigned a0 = __float_as_uint(Ps[ r0l      * 64 + c0 + t]);
            unsigned a2 = __float_as_uint(Ps[ r0l      * 64 + c1 + t]);
            unsigned a1 = __float_as_uint(Ps[(r0l + 8) * 64 + c0 + t]);
            unsigned a3 = __float_as_uint(Ps[(r0l + 8) * 64 + c1 + t]);
            const int kr  = 8 * o + t;
            const int kr2 = kr + 4;
#pragma unroll
            for (int j = 0; j < 8; j++) {
                int ch = 2 * j + (g >> 2);
                unsigned b0 = __float_as_uint(Vs[kr  * 64 + ((ch ^ (kr  & 7)) << 2) + (g & 3)]);
                unsigned b1 = __float_as_uint(Vs[kr2 * 64 + ((ch ^ (kr2 & 7)) << 2) + (g & 3)]);
                MMA_TF32(o_[j], a0, a1, a2, a3, b0, b1);
            }
        }
        __syncwarp();                              // P reads done before next overwrite
    }

    // ---- epilogue: fold padded keys, normalize, store ----
    const float npad = (float)(MAXLEN - L);
    float mf0 = (npad > 0.f) ? fmaxf(m0, 0.f) : m0;
    float mf1 = (npad > 0.f) ? fmaxf(m1, 0.f) : m1;
    float sc0 = __expf(m0 - mf0), sc1 = __expf(m1 - mf1);
    float w0 = sc0 / (l0 * sc0 + npad * __expf(-mf0));
    float w1 = sc1 / (l1 * sc1 + npad * __expf(-mf1));

    const int row0 = qt + r0l, row1 = row0 + 8;
#pragma unroll
    for (int j = 0; j < 8; j++) {
        int cn = h * HDD + j * 8 + 2 * t;
        *(float2*)&g_attn[(size_t)row0 * DIMM + cn] = make_float2(o_[j][0] * w0, o_[j][1] * w0);
        *(float2*)&g_attn[(size_t)row1 * DIMM + cn] = make_float2(o_[j][2] * w1, o_[j][3] * w1);
    }
}

// ---------------------------------------------------------------------------
extern "C" void kernel_launch(void* const* d_in, const int* in_sizes, int n_in,
                              void* d_out, int out_size)
{
    const float* hs   = (const float*)d_in[0];
    const float* wqkv = (const float*)d_in[1];
    const float* wo   = (const float*)d_in[2];
    const int*   cu   = (const int*)  d_in[3];
    float* out = (float*)d_out;

    float *qkv_p = nullptr, *attn_p = nullptr;
    cudaGetSymbolAddress((void**)&qkv_p,  g_qkv);
    cudaGetSymbolAddress((void**)&attn_p, g_attn);

    const int gemm_smem = 2 * 2 * 128 * 32 * 4;      // 65536
    const int attn_smem = (8192 + 4096 + 4096 + 8192) * 4;  // 98304
    cudaFuncSetAttribute(tf32_gemm_nt, cudaFuncAttributeMaxDynamicSharedMemorySize, gemm_smem);
    cudaFuncSetAttribute(attn_kernel,  cudaFuncAttributeMaxDynamicSharedMemorySize, attn_smem);

    // 1) QKV projection
    tf32_gemm_nt<<<dim3(NQKV / 128, TOTAL / 128), 256, gemm_smem>>>(
        hs, wqkv, qkv_p, TOTAL, NQKV, DIMM);
    // 2) RoPE
    rope_kernel<<<(TOTAL * 2 * NH * 32) / 256, 256>>>(cu);
    // 3) attention
    attn_kernel<<<dim3(TOTAL / 128, NH), 256, attn_smem>>>(cu);
    // 4) output projection
    tf32_gemm_nt<<<dim3(DIMM / 128, TOTAL / 128), 256, gemm_smem>>>(
        attn_p, wo, out, TOTAL, DIMM, DIMM);
}

// round 6
// speedup vs baseline: 3.2856x; 1.1166x over previous
#include <cuda_runtime.h>
#include <math.h>
#include <stdint.h>

#define TOTAL   5120
#define DIMM    1024
#define NH      16
#define HDD     64
#define NB      4
#define MAXLEN  2048
#define NQKV    3072

// tcgen05 only exists on arch-specific/feature sm_103a/sm_100a targets.
#if defined(__CUDA_ARCH__) && (__CUDA_ARCH__ >= 1000) && \
    (defined(__CUDA_ARCH_FEAT_SM103_ALL) || defined(__CUDA_ARCH_FEAT_SM100_ALL))
#define TC_OK 1
#else
#define TC_OK 0
#endif

// Scratch (device globals: no allocation allowed)
__device__ float g_qkv[(size_t)TOTAL * NQKV];    // q|k|v (tf32 values)
__device__ float g_attn[(size_t)TOTAL * DIMM];   // attention out (tf32 values)
__device__ float g_a [(size_t)TOTAL * DIMM];     // hs rounded to tf32
__device__ float g_w1[(size_t)NQKV * DIMM];      // Wqkv rounded to tf32
__device__ float g_w2[(size_t)DIMM * DIMM];      // Wo rounded to tf32
__device__ int   g_flag;                         // 1 => tcgen05 path bad, use fallback

extern __shared__ __align__(1024) uint8_t dynraw[];

__device__ __forceinline__ unsigned tf32r(float x) {
    unsigned u;
    asm("cvt.rna.tf32.f32 %0, %1;" : "=r"(u) : "f"(x));
    return u;
}
__device__ __forceinline__ float tf32rf(float x) {
    return __uint_as_float(tf32r(x));
}

// ---------------------------------------------------------------------------
// Elementwise round-to-tf32 copy (vectorized).
// ---------------------------------------------------------------------------
__global__ void __launch_bounds__(256) cvt_tf32(const float* __restrict__ src,
                                                float* __restrict__ dst, int n4)
{
    int i = blockIdx.x * 256 + threadIdx.x;
    if (i >= n4) return;
    float4 v = ((const float4*)src)[i];
    v.x = tf32rf(v.x); v.y = tf32rf(v.y);
    v.z = tf32rf(v.z); v.w = tf32rf(v.w);
    ((float4*)dst)[i] = v;
}

// ---------------------------------------------------------------------------
// Flag management + GEMM spot-check (4096 sampled dot products).
// ---------------------------------------------------------------------------
__global__ void zero_flag_kernel() { g_flag = 0; }

__global__ void __launch_bounds__(256) check_gemm(
    const float* __restrict__ A, const float* __restrict__ Bw,
    const float* __restrict__ C, int M, int N, int K)
{
    int s = blockIdx.x * 256 + threadIdx.x;      // 4096 samples
    int row = (int)(((unsigned)s * 2654435761u) % (unsigned)M);
    int col = (int)(((unsigned)s * 40503u + 17u) % (unsigned)N);
    const float* a = &A[(size_t)row * K];
    const float* b = &Bw[(size_t)col * K];
    float ref = 0.f;
    for (int k = 0; k < K; k += 4) {
        float4 av = *(const float4*)&a[k];
        float4 bv = *(const float4*)&b[k];
        ref += av.x * bv.x + av.y * bv.y + av.z * bv.z + av.w * bv.w;
    }
    float got = C[(size_t)row * N + col];
    if (fabsf(got - ref) > 1e-2f * (1.0f + fabsf(ref)))
        atomicOr(&g_flag, 1);
}

// ===========================================================================
// Path A: tcgen05 GEMM (body only on sm_103a/sm_100a feature targets).
// 256x256 CTA tile, K staged 32/buffer, 3-stage cp.async ring, TMEM D.
// ALL shared state in the dynamic region (1024-aligned tiles for SW128):
//   [0:16)   two mbarriers   [16:20) tmem ptr   [1024 : 1024+3*64K) tiles
// ===========================================================================
__global__ void __launch_bounds__(256, 1) tc_gemm_nt(
    const float* __restrict__ A, const float* __restrict__ Bw,
    float* __restrict__ C, int M, int N, int K, int round_out)
{
#if TC_OK
    const int tid = threadIdx.x;
    const int wid = tid >> 5;
    const int bm = blockIdx.y * 256, bn = blockIdx.x * 256;

    const uint32_t sbase = (uint32_t)__cvta_generic_to_shared(dynraw);
    const uint32_t mbar0 = sbase;
    const uint32_t tptr  = sbase + 16;
    const uint32_t tile0 = sbase + 1024;

    if (wid == 0) {
        asm volatile("tcgen05.alloc.cta_group::1.sync.aligned.shared::cta.b32 [%0], %1;"
                     :: "r"(tptr), "r"(512u) : "memory");
        asm volatile("tcgen05.relinquish_alloc_permit.cta_group::1.sync.aligned;");
    }
    if (tid == 0) {
        asm volatile("mbarrier.init.shared.b64 [%0], 1;" :: "r"(mbar0) : "memory");
        asm volatile("mbarrier.init.shared.b64 [%0], 1;" :: "r"(mbar0 + 8) : "memory");
    }
    __syncthreads();
    uint32_t tmem;
    asm volatile("ld.shared.b32 %0, [%1];" : "=r"(tmem) : "r"(tptr));

    const uint64_t desc_base = (uint64_t(2) << 61) | (uint64_t(1) << 46)
                             | (uint64_t(64) << 32) | (uint64_t(1) << 16);
    const uint32_t idesc = (1u << 4) | (2u << 7) | (2u << 10)
                         | ((256u / 8) << 17) | ((128u / 16) << 24);

    const int T = K >> 5;

#define TC_STAGE(j)                                                           \
    {                                                                         \
        if ((j) < T) {                                                        \
            uint32_t buf = tile0 + ((j) % 3) * 65536u;                        \
            int k0 = (j) << 5;                                                \
            _Pragma("unroll")                                                 \
            for (int it = 0; it < 8; it++) {                                  \
                int id = tid + 256 * it;                                      \
                int row = id >> 3, c = id & 7;                                \
                uint32_t off = buf + (uint32_t)(row * 128 + ((c ^ (row & 7)) << 4)); \
                asm volatile("cp.async.ca.shared.global [%0],[%1],16;\n"      \
                             :: "r"(off), "l"(&A[(size_t)(bm + row) * K + k0 + c * 4])); \
                asm volatile("cp.async.ca.shared.global [%0],[%1],16;\n"      \
                             :: "r"(off + 32768u), "l"(&Bw[(size_t)(bn + row) * K + k0 + c * 4])); \
            }                                                                 \
        }                                                                     \
        asm volatile("cp.async.commit_group;\n");                            \
    }
#define TC_MWAIT(j)                                                           \
    {                                                                         \
        uint32_t ad = mbar0 + (((j) & 1) << 3);                               \
        uint32_t pr = ((j) >> 1) & 1;                                         \
        asm volatile("{\n\t.reg .pred P1;\n\t"                                \
                     "W_%=:\n\t"                                              \
                     "mbarrier.try_wait.parity.acquire.cta.shared::cta.b64 P1, [%0], %1, 0x989680;\n\t" \
                     "@P1 bra.uni D_%=;\n\t"                                  \
                     "bra.uni W_%=;\n\t"                                      \
                     "D_%=:\n\t}" :: "r"(ad), "r"(pr) : "memory");            \
    }

    TC_STAGE(0);
    TC_STAGE(1);

    for (int i = 0; i < T; i++) {
        if (i >= 1) TC_MWAIT(i - 1);           // MMA i-1 done => buffer (i-1)%3 free
        TC_STAGE(i + 2);
        asm volatile("cp.async.wait_group 2;\n");
        __syncthreads();
        if (wid == 0) {
            asm volatile("fence.proxy.async.shared::cta;" ::: "memory");
            uint32_t one;
            asm volatile("{\n\t.reg .pred p;\n\telect.sync _|p, 0xFFFFFFFF;\n\t"
                         "selp.b32 %0, 1, 0, p;\n\t}" : "=r"(one));
            if (one) {
                uint32_t buf = tile0 + (i % 3) * 65536u;
                uint64_t ad = desc_base | ((uint64_t)(buf >> 4) & 0x3FFF);
                uint64_t bd = desc_base | ((uint64_t)((buf + 32768u) >> 4) & 0x3FFF);
#pragma unroll
                for (int ks = 0; ks < 4; ks++) {
                    uint32_t en = (i > 0) || (ks > 0);
                    asm volatile("{\n\t.reg .pred p;\n\tsetp.ne.u32 p, %4, 0;\n\t"
                                 "tcgen05.mma.cta_group::1.kind::tf32 [%0], %1, %2, %3, {%5,%5,%5,%5}, p;\n\t}"
                                 :: "r"(tmem), "l"(ad + ks * 2), "l"(bd + ks * 2),
                                    "r"(idesc), "r"(en), "r"(0u) : "memory");
                    asm volatile("{\n\t.reg .pred p;\n\tsetp.ne.u32 p, %4, 0;\n\t"
                                 "tcgen05.mma.cta_group::1.kind::tf32 [%0], %1, %2, %3, {%5,%5,%5,%5}, p;\n\t}"
                                 :: "r"(tmem + 256), "l"(ad + 1024 + ks * 2), "l"(bd + ks * 2),
                                    "r"(idesc), "r"(en), "r"(0u) : "memory");
                }
                asm volatile("tcgen05.commit.cta_group::1.mbarrier::arrive::one.shared::cluster.b64 [%0];"
                             :: "r"(mbar0 + ((i & 1) << 3)) : "memory");
            }
        }
    }
    TC_MWAIT(T - 1);
    asm volatile("tcgen05.fence::after_thread_sync;" ::: "memory");

    {
        const int w4 = wid & 3, half = wid >> 2;
        const uint32_t warp_off = ((uint32_t)w4) << 21;
        const uint32_t col0 = half * 256;
        const int grow = bm + half * 128 + w4 * 32 + (tid & 31);
#pragma unroll
        for (int ch = 0; ch < 8; ch++) {
            uint32_t r[32];
            asm volatile("tcgen05.ld.sync.aligned.32x32b.x32.b32 "
                "{%0, %1, %2, %3, %4, %5, %6, %7, "
                " %8, %9, %10, %11, %12, %13, %14, %15, "
                " %16, %17, %18, %19, %20, %21, %22, %23, "
                " %24, %25, %26, %27, %28, %29, %30, %31}, [%32];"
                : "=r"(r[0]),  "=r"(r[1]),  "=r"(r[2]),  "=r"(r[3]),
                  "=r"(r[4]),  "=r"(r[5]),  "=r"(r[6]),  "=r"(r[7]),
                  "=r"(r[8]),  "=r"(r[9]),  "=r"(r[10]), "=r"(r[11]),
                  "=r"(r[12]), "=r"(r[13]), "=r"(r[14]), "=r"(r[15]),
                  "=r"(r[16]), "=r"(r[17]), "=r"(r[18]), "=r"(r[19]),
                  "=r"(r[20]), "=r"(r[21]), "=r"(r[22]), "=r"(r[23]),
                  "=r"(r[24]), "=r"(r[25]), "=r"(r[26]), "=r"(r[27]),
                  "=r"(r[28]), "=r"(r[29]), "=r"(r[30]), "=r"(r[31])
                : "r"(tmem + warp_off + col0 + ch * 32));
            asm volatile("tcgen05.wait::ld.sync.aligned;" ::: "memory");
            float* cp = &C[(size_t)grow * N + bn + ch * 32];
            if (round_out) {
#pragma unroll
                for (int q = 0; q < 8; q++)
                    *(float4*)&cp[q * 4] = make_float4(
                        tf32rf(__uint_as_float(r[q * 4 + 0])), tf32rf(__uint_as_float(r[q * 4 + 1])),
                        tf32rf(__uint_as_float(r[q * 4 + 2])), tf32rf(__uint_as_float(r[q * 4 + 3])));
            } else {
#pragma unroll
                for (int q = 0; q < 8; q++)
                    *(float4*)&cp[q * 4] = make_float4(
                        __uint_as_float(r[q * 4 + 0]), __uint_as_float(r[q * 4 + 1]),
                        __uint_as_float(r[q * 4 + 2]), __uint_as_float(r[q * 4 + 3]));
            }
        }
    }
    __syncthreads();
    if (wid == 0)
        asm volatile("tcgen05.dealloc.cta_group::1.sync.aligned.b32 %0, %1;"
                     :: "r"(tmem), "r"(512u));
#endif  // TC_OK
}

// ===========================================================================
// Path B: mma.sync tf32 GEMM fallback — ALWAYS compiled; runs only when
// g_flag != 0 (tcgen05 output failed the spot check or never ran).
// ===========================================================================
#define MMA_TF32(acc, a0,a1,a2,a3, b0,b1)                                     \
    asm volatile("mma.sync.aligned.m16n8k8.row.col.f32.tf32.tf32.f32 "        \
                 "{%0,%1,%2,%3}, {%4,%5,%6,%7}, {%8,%9}, {%0,%1,%2,%3};"      \
                 : "+f"((acc)[0]), "+f"((acc)[1]), "+f"((acc)[2]), "+f"((acc)[3]) \
                 : "r"(a0), "r"(a1), "r"(a2), "r"(a3), "r"(b0), "r"(b1))

__global__ void __launch_bounds__(256, 2) mma_gemm_nt(
    const float* __restrict__ A, const float* __restrict__ Bw,
    float* __restrict__ C, int M, int N, int K, int round_out)
{
    if (g_flag == 0) return;                     // tcgen05 result verified good

    float* As = (float*)dynraw;                  // [2][128*32]
    float* Bs = (float*)dynraw + 8192;

    const int tid  = threadIdx.x;
    const int lane = tid & 31, w = tid >> 5;
    const int g = lane >> 2, t = lane & 3;
    const int wm = w >> 2, wn = w & 3;
    const int bm = blockIdx.y * 128, bn = blockIdx.x * 128;

    float acc[4][4][4] = {};

    const unsigned sA0 = (unsigned)__cvta_generic_to_shared(As);
    const unsigned sB0 = (unsigned)__cvta_generic_to_shared(Bs);

#define GEMM_STAGE(buf, k0)                                                   \
    {                                                                         \
        unsigned sa = sA0 + (buf) * 16384, sb = sB0 + (buf) * 16384;          \
        _Pragma("unroll")                                                     \
        for (int it = 0; it < 4; it++) {                                      \
            int id = tid + 256 * it;                                          \
            int row = id >> 3, c = id & 7;                                    \
            unsigned off = (unsigned)(row * 32 + ((c ^ (row & 7)) << 2)) * 4; \
            asm volatile("cp.async.ca.shared.global [%0],[%1],16;\n"          \
                         :: "r"(sa + off), "l"(&A [(size_t)(bm + row) * K + (k0) + c * 4])); \
            asm volatile("cp.async.ca.shared.global [%0],[%1],16;\n"          \
                         :: "r"(sb + off), "l"(&Bw[(size_t)(bn + row) * K + (k0) + c * 4])); \
        }                                                                     \
        asm volatile("cp.async.commit_group;\n");                             \
    }

    GEMM_STAGE(0, 0);
    int buf = 0;
    for (int k0 = 0; k0 < K; k0 += 32) {
        asm volatile("cp.async.wait_group 0;\n");
        __syncthreads();
        if (k0 + 32 < K) GEMM_STAGE(buf ^ 1, k0 + 32);

        const float* Ab = As + buf * 4096;
        const float* Bb = Bs + buf * 4096;
#pragma unroll
        for (int o = 0; o < 4; o++) {
            const int c0 = ((2 * o) ^ g) << 2, c1 = ((2 * o + 1) ^ g) << 2;
            unsigned a[4][4], b[4][2];
#pragma unroll
            for (int mt = 0; mt < 4; mt++) {
                int r0 = wm * 64 + mt * 16 + g;
                a[mt][0] = __float_as_uint(Ab[ r0      * 32 + c0 + t]);
                a[mt][2] = __float_as_uint(Ab[ r0      * 32 + c1 + t]);
                a[mt][1] = __float_as_uint(Ab[(r0 + 8) * 32 + c0 + t]);
                a[mt][3] = __float_as_uint(Ab[(r0 + 8) * 32 + c1 + t]);
            }
#pragma unroll
            for (int nt = 0; nt < 4; nt++) {
                int r0 = wn * 32 + nt * 8 + g;
                b[nt][0] = __float_as_uint(Bb[r0 * 32 + c0 + t]);
                b[nt][1] = __float_as_uint(Bb[r0 * 32 + c1 + t]);
            }
#pragma unroll
            for (int mt = 0; mt < 4; mt++)
#pragma unroll
                for (int nt = 0; nt < 4; nt++)
                    MMA_TF32(acc[mt][nt], a[mt][0], a[mt][1], a[mt][2], a[mt][3],
                             b[nt][0], b[nt][1]);
        }
        buf ^= 1;
    }

#pragma unroll
    for (int mt = 0; mt < 4; mt++) {
        int r = bm + wm * 64 + mt * 16 + g;
#pragma unroll
        for (int nt = 0; nt < 4; nt++) {
            int cn = bn + wn * 32 + nt * 8 + 2 * t;
            float v0 = acc[mt][nt][0], v1 = acc[mt][nt][1];
            float v2 = acc[mt][nt][2], v3 = acc[mt][nt][3];
            if (round_out) {
                v0 = tf32rf(v0); v1 = tf32rf(v1); v2 = tf32rf(v2); v3 = tf32rf(v3);
            }
            *(float2*)&C[(size_t)r * N + cn]       = make_float2(v0, v1);
            *(float2*)&C[(size_t)(r + 8) * N + cn] = make_float2(v2, v3);
        }
    }
}

// ---------------------------------------------------------------------------
// RoPE in-place on q,k sections of g_qkv; outputs rounded to tf32.
// ---------------------------------------------------------------------------
__global__ void __launch_bounds__(256) rope_kernel(const int* __restrict__ cu)
{
    int tt = blockIdx.x * 256 + threadIdx.x;
    int j  = tt & 31;
    int hh = (tt >> 5) & 15;
    int s  = (tt >> 9) & 1;
    int r  = tt >> 10;
    if (r >= TOTAL) return;

    int b = 0;
#pragma unroll
    for (int i = 1; i < NB; i++) if (r >= cu[i]) b = i;
    int pos = r - cu[b];

    float inv = exp2f(-(float)j * (13.287712379549449f / 32.0f));
    float fr  = (float)pos * inv;
    float c, sn;
    sincosf(fr, &sn, &c);

    float* base = g_qkv + (size_t)r * NQKV + s * DIMM + hh * HDD;
    float x1 = base[j], x2 = base[j + 32];
    base[j]      = tf32rf(x1 * c - x2 * sn);
    base[j + 32] = tf32rf(x2 * c + x1 * sn);
}

// ---------------------------------------------------------------------------
// Tensor-core flash attention (tf32, mma.sync). g_qkv holds tf32 values so
// staging is pure copies (Q x 0.125 exact). Output tf32-rounded for GEMM2.
// ---------------------------------------------------------------------------
__global__ void __launch_bounds__(256, 2) attn_kernel(const int* __restrict__ cu)
{
    float* Qs = (float*)dynraw;             // 128*64
    float* Ks = (float*)dynraw + 8192;      // 64*64
    float* Vs = (float*)dynraw + 12288;     // 64*64
    float* Ps = (float*)dynraw + 16384;     // 128*64

    const int tid  = threadIdx.x;
    const int lane = tid & 31, w = tid >> 5;
    const int g = lane >> 2, t = lane & 3;
    const int h  = blockIdx.y;
    const int qt = blockIdx.x * 128;

    int b = 0;
#pragma unroll
    for (int i = 1; i < NB; i++) if (qt >= cu[i]) b = i;
    const int base = cu[b];
    const int L    = cu[b + 1] - base;

#pragma unroll
    for (int it = 0; it < 8; it++) {
        int id = tid + 256 * it;
        int row = id >> 4, c = id & 15;
        float4 v = *(const float4*)&g_qkv[(size_t)(qt + row) * NQKV + h * HDD + c * 4];
        float* d = &Qs[row * 64 + ((c ^ (row & 7)) << 2)];
        d[0] = v.x * 0.125f; d[1] = v.y * 0.125f;
        d[2] = v.z * 0.125f; d[3] = v.w * 0.125f;
    }

    const int r0l = w * 16 + g;
    float m0 = -1e30f, m1 = -1e30f, l0 = 0.f, l1 = 0.f;
    float o_[8][4] = {};

    const int nkt = L >> 6;
    for (int kt = 0; kt < nkt; kt++) {
        __syncthreads();
        const size_t kr0 = (size_t)(base + kt * 64);
#pragma unroll
        for (int it = 0; it < 4; it++) {
            int id = tid + 256 * it;
            int row = id >> 4, c = id & 15;
            const float* src = &g_qkv[(kr0 + row) * NQKV + h * HDD + c * 4];
            float4 kv = *(const float4*)&src[DIMM];
            float4 vv = *(const float4*)&src[2 * DIMM];
            *(float4*)&Ks[row * 64 + ((c ^ (row & 7)) << 2)] = kv;
            *(float4*)&Vs[row * 64 + ((c ^ (row & 7)) << 2)] = vv;
        }
        __syncthreads();

        float s[8][4] = {};
#pragma unroll
        for (int o = 0; o < 8; o++) {
            const int c0 = ((2 * o) ^ g) << 2, c1 = ((2 * o + 1) ^ g) << 2;
            unsigned a0 = __float_as_uint(Qs[ r0l      * 64 + c0 + t]);
            unsigned a2 = __float_as_uint(Qs[ r0l      * 64 + c1 + t]);
            unsigned a1 = __float_as_uint(Qs[(r0l + 8) * 64 + c0 + t]);
            unsigned a3 = __float_as_uint(Qs[(r0l + 8) * 64 + c1 + t]);
#pragma unroll
            for (int j = 0; j < 8; j++) {
                int rb = j * 8 + g;
                unsigned b0 = __float_as_uint(Ks[rb * 64 + c0 + t]);
                unsigned b1 = __float_as_uint(Ks[rb * 64 + c1 + t]);
                MMA_TF32(s[j], a0, a1, a2, a3, b0, b1);
            }
        }

        float rm0 = -1e30f, rm1 = -1e30f;
#pragma unroll
        for (int j = 0; j < 8; j++) {
            rm0 = fmaxf(rm0, fmaxf(s[j][0], s[j][1]));
            rm1 = fmaxf(rm1, fmaxf(s[j][2], s[j][3]));
        }
#pragma unroll
        for (int off = 1; off < 4; off <<= 1) {
            rm0 = fmaxf(rm0, __shfl_xor_sync(0xffffffffu, rm0, off));
            rm1 = fmaxf(rm1, __shfl_xor_sync(0xffffffffu, rm1, off));
        }
        float mn0 = fmaxf(m0, rm0), mn1 = fmaxf(m1, rm1);
        float f0 = __expf(m0 - mn0), f1 = __expf(m1 - mn1);
        float rs0 = 0.f, rs1 = 0.f;
#pragma unroll
        for (int j = 0; j < 8; j++) {
            s[j][0] = __expf(s[j][0] - mn0); rs0 += s[j][0];
            s[j][1] = __expf(s[j][1] - mn0); rs0 += s[j][1];
            s[j][2] = __expf(s[j][2] - mn1); rs1 += s[j][2];
            s[j][3] = __expf(s[j][3] - mn1); rs1 += s[j][3];
        }
#pragma unroll
        for (int off = 1; off < 4; off <<= 1) {
            rs0 += __shfl_xor_sync(0xffffffffu, rs0, off);
            rs1 += __shfl_xor_sync(0xffffffffu, rs1, off);
        }
        l0 = l0 * f0 + rs0;  m0 = mn0;
        l1 = l1 * f1 + rs1;  m1 = mn1;
#pragma unroll
        for (int j = 0; j < 8; j++) {
            o_[j][0] *= f0; o_[j][1] *= f0;
            o_[j][2] *= f1; o_[j][3] *= f1;
        }

#pragma unroll
        for (int j = 0; j < 8; j++) {
            int ch = 2 * j + (t >> 1);
            int wd = 2 * (t & 1);
            float* p0 = &Ps[ r0l      * 64 + ((ch ^ g) << 2) + wd];
            p0[0] = tf32rf(s[j][0]);
            p0[1] = tf32rf(s[j][1]);
            float* p1 = &Ps[(r0l + 8) * 64 + ((ch ^ g) << 2) + wd];
            p1[0] = tf32rf(s[j][2]);
            p1[1] = tf32rf(s[j][3]);
        }
        __syncwarp();

#pragma unroll
        for (int o = 0; o < 8; o++) {
            const int c0 = ((2 * o) ^ g) << 2, c1 = ((2 * o + 1) ^ g) << 2;
            unsigned a0 = __float_as_uint(Ps[ r0l      * 64 + c0 + t]);
            unsigned a2 = __float_as_uint(Ps[ r0l      * 64 + c1 + t]);
            unsigned a1 = __float_as_uint(Ps[(r0l + 8) * 64 + c0 + t]);
            unsigned a3 = __float_as_uint(Ps[(r0l + 8) * 64 + c1 + t]);
            const int kr  = 8 * o + t;
            const int kr2 = kr + 4;
#pragma unroll
            for (int j = 0; j < 8; j++) {
                int ch = 2 * j + (g >> 2);
                unsigned b0 = __float_as_uint(Vs[kr  * 64 + ((ch ^ (kr  & 7)) << 2) + (g & 3)]);
                unsigned b1 = __float_as_uint(Vs[kr2 * 64 + ((ch ^ (kr2 & 7)) << 2) + (g & 3)]);
                MMA_TF32(o_[j], a0, a1, a2, a3, b0, b1);
            }
        }
        __syncwarp();
    }

    const float npad = (float)(MAXLEN - L);
    float mf0 = (npad > 0.f) ? fmaxf(m0, 0.f) : m0;
    float mf1 = (npad > 0.f) ? fmaxf(m1, 0.f) : m1;
    float sc0 = __expf(m0 - mf0), sc1 = __expf(m1 - mf1);
    float w0 = sc0 / (l0 * sc0 + npad * __expf(-mf0));
    float w1 = sc1 / (l1 * sc1 + npad * __expf(-mf1));

    const int row0 = qt + r0l, row1 = row0 + 8;
#pragma unroll
    for (int j = 0; j < 8; j++) {
        int cn = h * HDD + j * 8 + 2 * t;
        *(float2*)&g_attn[(size_t)row0 * DIMM + cn] = make_float2(
            tf32rf(o_[j][0] * w0), tf32rf(o_[j][1] * w0));
        *(float2*)&g_attn[(size_t)row1 * DIMM + cn] = make_float2(
            tf32rf(o_[j][2] * w1), tf32rf(o_[j][3] * w1));
    }
}

// ---------------------------------------------------------------------------
extern "C" void kernel_launch(void* const* d_in, const int* in_sizes, int n_in,
                              void* d_out, int out_size)
{
    const float* hs   = (const float*)d_in[0];
    const float* wqkv = (const float*)d_in[1];
    const float* wo   = (const float*)d_in[2];
    const int*   cu   = (const int*)  d_in[3];
    float* out = (float*)d_out;

    float *qkv_p, *attn_p, *a_p, *w1_p, *w2_p;
    cudaGetSymbolAddress((void**)&qkv_p,  g_qkv);
    cudaGetSymbolAddress((void**)&attn_p, g_attn);
    cudaGetSymbolAddress((void**)&a_p,    g_a);
    cudaGetSymbolAddress((void**)&w1_p,   g_w1);
    cudaGetSymbolAddress((void**)&w2_p,   g_w2);

    const int tc_smem   = 1024 + 3 * 65536;   // 197632
    const int mma_smem  = 65536;
    const int attn_smem = 98304;
    cudaFuncSetAttribute(tc_gemm_nt,  cudaFuncAttributeMaxDynamicSharedMemorySize, tc_smem);
    cudaFuncSetAttribute(mma_gemm_nt, cudaFuncAttributeMaxDynamicSharedMemorySize, mma_smem);
    cudaFuncSetAttribute(attn_kernel, cudaFuncAttributeMaxDynamicSharedMemorySize, attn_smem);

    // 0) pre-round inputs/weights to tf32 (rna); reset flag
    zero_flag_kernel<<<1, 1>>>();
    cvt_tf32<<<(TOTAL * DIMM / 4 + 255) / 256, 256>>>(hs,   a_p,  TOTAL * DIMM / 4);
    cvt_tf32<<<(NQKV * DIMM / 4 + 255) / 256, 256>>>(wqkv, w1_p, NQKV * DIMM / 4);
    cvt_tf32<<<(DIMM * DIMM / 4 + 255) / 256, 256>>>(wo,   w2_p, DIMM * DIMM / 4);

    // 1) QKV projection: tcgen05 attempt -> spot check -> conditional fallback
    tc_gemm_nt <<<dim3(NQKV / 256, TOTAL / 256), 256, tc_smem >>>(
        a_p, w1_p, qkv_p, TOTAL, NQKV, DIMM, 1);
    check_gemm <<<16, 256>>>(a_p, w1_p, qkv_p, TOTAL, NQKV, DIMM);
    mma_gemm_nt<<<dim3(NQKV / 128, TOTAL / 128), 256, mma_smem>>>(
        a_p, w1_p, qkv_p, TOTAL, NQKV, DIMM, 1);

    // 2) RoPE (rounds q,k to tf32)
    rope_kernel<<<(TOTAL * 2 * NH * 32) / 256, 256>>>(cu);
    // 3) attention
    attn_kernel<<<dim3(TOTAL / 128, NH), 256, attn_smem>>>(cu);

    // 4) output projection (same flag governs fallback)
    tc_gemm_nt <<<dim3(DIMM / 256, TOTAL / 256), 256, tc_smem >>>(
        attn_p, w2_p, out, TOTAL, DIMM, DIMM, 0);
    mma_gemm_nt<<<dim3(DIMM / 128, TOTAL / 128), 256, mma_smem>>>(
        attn_p, w2_p, out, TOTAL, DIMM, DIMM, 0);
}

// round 7
// speedup vs baseline: 3.3451x; 1.0181x over previous
#include <cuda_runtime.h>
#include <math.h>
#include <stdint.h>

#define TOTAL   5120
#define DIMM    1024
#define NH      16
#define HDD     64
#define NB      4
#define MAXLEN  2048
#define NQKV    3072

// tcgen05 only exists on arch-specific/feature sm_103a/sm_100a targets.
#if defined(__CUDA_ARCH__) && (__CUDA_ARCH__ >= 1000) && \
    (defined(__CUDA_ARCH_FEAT_SM103_ALL) || defined(__CUDA_ARCH_FEAT_SM100_ALL))
#define TC_OK 1
#else
#define TC_OK 0
#endif

// Scratch (device globals: no allocation allowed)
__device__ float g_qkv[(size_t)TOTAL * NQKV];    // q|k|v (tf32 values)
__device__ float g_attn[(size_t)TOTAL * DIMM];   // attention out (tf32 values)
__device__ float g_a [(size_t)TOTAL * DIMM];     // hs rounded to tf32
__device__ float g_w1[(size_t)NQKV * DIMM];      // Wqkv rounded to tf32
__device__ float g_w2[(size_t)DIMM * DIMM];      // Wo rounded to tf32
__device__ int   g_flag;                         // 1 => tcgen05 path bad, use fallback

extern __shared__ __align__(1024) uint8_t dynraw[];

__device__ __forceinline__ unsigned tf32r(float x) {
    unsigned u;
    asm("cvt.rna.tf32.f32 %0, %1;" : "=r"(u) : "f"(x));
    return u;
}
__device__ __forceinline__ float tf32rf(float x) {
    return __uint_as_float(tf32r(x));
}

// ---------------------------------------------------------------------------
// Elementwise round-to-tf32 copy (vectorized).
// ---------------------------------------------------------------------------
__global__ void __launch_bounds__(256) cvt_tf32(const float* __restrict__ src,
                                                float* __restrict__ dst, int n4)
{
    int i = blockIdx.x * 256 + threadIdx.x;
    if (i >= n4) return;
    float4 v = ((const float4*)src)[i];
    v.x = tf32rf(v.x); v.y = tf32rf(v.y);
    v.z = tf32rf(v.z); v.w = tf32rf(v.w);
    ((float4*)dst)[i] = v;
}

// ---------------------------------------------------------------------------
// Flag management + GEMM spot-check (4096 sampled dot products).
// ---------------------------------------------------------------------------
__global__ void zero_flag_kernel() { g_flag = 0; }

__global__ void __launch_bounds__(256) check_gemm(
    const float* __restrict__ A, const float* __restrict__ Bw,
    const float* __restrict__ C, int M, int N, int K)
{
    int s = blockIdx.x * 256 + threadIdx.x;      // 4096 samples
    int row = (int)(((unsigned)s * 2654435761u) % (unsigned)M);
    int col = (int)(((unsigned)s * 40503u + 17u) % (unsigned)N);
    const float* a = &A[(size_t)row * K];
    const float* b = &Bw[(size_t)col * K];
    float ref = 0.f;
    for (int k = 0; k < K; k += 4) {
        float4 av = *(const float4*)&a[k];
        float4 bv = *(const float4*)&b[k];
        ref += av.x * bv.x + av.y * bv.y + av.z * bv.z + av.w * bv.w;
    }
    float got = C[(size_t)row * N + col];
    if (fabsf(got - ref) > 1e-2f * (1.0f + fabsf(ref)))
        atomicOr(&g_flag, 1);
}

// ===========================================================================
// Path A: tcgen05 GEMM (body only on sm_103a/sm_100a feature targets).
// 256x256 CTA tile, K staged 32/buffer, 3-stage cp.async ring, TMEM D.
// Dynamic smem: [0:16) two mbarriers, [16:20) tmem ptr, [1024:...) tiles.
// Producer pattern per iteration: cp.async.wait_group -> fence.proxy.async
// (ALL threads) -> __syncthreads -> elected thread issues MMAs.
// ===========================================================================
__global__ void __launch_bounds__(256, 1) tc_gemm_nt(
    const float* __restrict__ A, const float* __restrict__ Bw,
    float* __restrict__ C, int M, int N, int K, int round_out)
{
#if TC_OK
    const int tid = threadIdx.x;
    const int wid = tid >> 5;
    const int bm = blockIdx.y * 256, bn = blockIdx.x * 256;

    const uint32_t sbase = (uint32_t)__cvta_generic_to_shared(dynraw);
    const uint32_t mbar0 = sbase;
    const uint32_t tptr  = sbase + 16;
    const uint32_t tile0 = sbase + 1024;

    if (wid == 0) {
        asm volatile("tcgen05.alloc.cta_group::1.sync.aligned.shared::cta.b32 [%0], %1;"
                     :: "r"(tptr), "r"(512u) : "memory");
        asm volatile("tcgen05.relinquish_alloc_permit.cta_group::1.sync.aligned;");
    }
    if (tid == 0) {
        asm volatile("mbarrier.init.shared.b64 [%0], 1;" :: "r"(mbar0) : "memory");
        asm volatile("mbarrier.init.shared.b64 [%0], 1;" :: "r"(mbar0 + 8) : "memory");
    }
    __syncthreads();
    uint32_t tmem;
    asm volatile("ld.shared.b32 %0, [%1];" : "=r"(tmem) : "r"(tptr));

    const uint64_t desc_base = (uint64_t(2) << 61) | (uint64_t(1) << 46)
                             | (uint64_t(64) << 32) | (uint64_t(1) << 16);
    const uint32_t idesc = (1u << 4) | (2u << 7) | (2u << 10)
                         | ((256u / 8) << 17) | ((128u / 16) << 24);

    const int T = K >> 5;

#define TC_STAGE(j)                                                           \
    {                                                                         \
        if ((j) < T) {                                                        \
            uint32_t buf = tile0 + ((j) % 3) * 65536u;                        \
            int k0 = (j) << 5;                                                \
            _Pragma("unroll")                                                 \
            for (int it = 0; it < 8; it++) {                                  \
                int id = tid + 256 * it;                                      \
                int row = id >> 3, c = id & 7;                                \
                uint32_t off = buf + (uint32_t)(row * 128 + ((c ^ (row & 7)) << 4)); \
                asm volatile("cp.async.ca.shared.global [%0],[%1],16;\n"      \
                             :: "r"(off), "l"(&A[(size_t)(bm + row) * K + k0 + c * 4])); \
                asm volatile("cp.async.ca.shared.global [%0],[%1],16;\n"      \
                             :: "r"(off + 32768u), "l"(&Bw[(size_t)(bn + row) * K + k0 + c * 4])); \
            }                                                                 \
        }                                                                     \
        asm volatile("cp.async.commit_group;\n");                            \
    }
#define TC_MWAIT(j)                                                           \
    {                                                                         \
        uint32_t ad = mbar0 + (((j) & 1) << 3);                               \
        uint32_t pr = ((j) >> 1) & 1;                                         \
        asm volatile("{\n\t.reg .pred P1;\n\t"                                \
                     "W_%=:\n\t"                                              \
                     "mbarrier.try_wait.parity.acquire.cta.shared::cta.b64 P1, [%0], %1, 0x989680;\n\t" \
                     "@P1 bra.uni D_%=;\n\t"                                  \
                     "bra.uni W_%=;\n\t"                                      \
                     "D_%=:\n\t}" :: "r"(ad), "r"(pr) : "memory");            \
    }

    TC_STAGE(0);
    TC_STAGE(1);

    for (int i = 0; i < T; i++) {
        if (i >= 1) TC_MWAIT(i - 1);           // MMA i-1 done => buffer (i-1)%3 free
        TC_STAGE(i + 2);
        asm volatile("cp.async.wait_group 2;\n");
        // Producer-side proxy fence: every thread makes its generic-proxy
        // smem writes visible to the async proxy BEFORE the barrier.
        asm volatile("fence.proxy.async.shared::cta;" ::: "memory");
        __syncthreads();
        if (wid == 0) {
            uint32_t one;
            asm volatile("{\n\t.reg .pred p;\n\telect.sync _|p, 0xFFFFFFFF;\n\t"
                         "selp.b32 %0, 1, 0, p;\n\t}" : "=r"(one));
            if (one) {
                uint32_t buf = tile0 + (i % 3) * 65536u;
                uint64_t ad = desc_base | ((uint64_t)(buf >> 4) & 0x3FFF);
                uint64_t bd = desc_base | ((uint64_t)((buf + 32768u) >> 4) & 0x3FFF);
#pragma unroll
                for (int ks = 0; ks < 4; ks++) {
                    uint32_t en = (i > 0) || (ks > 0);
                    asm volatile("{\n\t.reg .pred p;\n\tsetp.ne.u32 p, %4, 0;\n\t"
                                 "tcgen05.mma.cta_group::1.kind::tf32 [%0], %1, %2, %3, {%5,%5,%5,%5}, p;\n\t}"
                                 :: "r"(tmem), "l"(ad + ks * 2), "l"(bd + ks * 2),
                                    "r"(idesc), "r"(en), "r"(0u) : "memory");
                    asm volatile("{\n\t.reg .pred p;\n\tsetp.ne.u32 p, %4, 0;\n\t"
                                 "tcgen05.mma.cta_group::1.kind::tf32 [%0], %1, %2, %3, {%5,%5,%5,%5}, p;\n\t}"
                                 :: "r"(tmem + 256), "l"(ad + 1024 + ks * 2), "l"(bd + ks * 2),
                                    "r"(idesc), "r"(en), "r"(0u) : "memory");
                }
                asm volatile("tcgen05.commit.cta_group::1.mbarrier::arrive::one.shared::cluster.b64 [%0];"
                             :: "r"(mbar0 + ((i & 1) << 3)) : "memory");
            }
        }
    }
    TC_MWAIT(T - 1);
    asm volatile("tcgen05.fence::after_thread_sync;" ::: "memory");

    {
        const int w4 = wid & 3, half = wid >> 2;
        const uint32_t warp_off = ((uint32_t)w4) << 21;
        const uint32_t col0 = half * 256;
        const int grow = bm + half * 128 + w4 * 32 + (tid & 31);
#pragma unroll
        for (int ch = 0; ch < 8; ch++) {
            uint32_t r[32];
            asm volatile("tcgen05.ld.sync.aligned.32x32b.x32.b32 "
                "{%0, %1, %2, %3, %4, %5, %6, %7, "
                " %8, %9, %10, %11, %12, %13, %14, %15, "
                " %16, %17, %18, %19, %20, %21, %22, %23, "
                " %24, %25, %26, %27, %28, %29, %30, %31}, [%32];"
                : "=r"(r[0]),  "=r"(r[1]),  "=r"(r[2]),  "=r"(r[3]),
                  "=r"(r[4]),  "=r"(r[5]),  "=r"(r[6]),  "=r"(r[7]),
                  "=r"(r[8]),  "=r"(r[9]),  "=r"(r[10]), "=r"(r[11]),
                  "=r"(r[12]), "=r"(r[13]), "=r"(r[14]), "=r"(r[15]),
                  "=r"(r[16]), "=r"(r[17]), "=r"(r[18]), "=r"(r[19]),
                  "=r"(r[20]), "=r"(r[21]), "=r"(r[22]), "=r"(r[23]),
                  "=r"(r[24]), "=r"(r[25]), "=r"(r[26]), "=r"(r[27]),
                  "=r"(r[28]), "=r"(r[29]), "=r"(r[30]), "=r"(r[31])
                : "r"(tmem + warp_off + col0 + ch * 32));
            asm volatile("tcgen05.wait::ld.sync.aligned;" ::: "memory");
            float* cp = &C[(size_t)grow * N + bn + ch * 32];
            if (round_out) {
#pragma unroll
                for (int q = 0; q < 8; q++)
                    *(float4*)&cp[q * 4] = make_float4(
                        tf32rf(__uint_as_float(r[q * 4 + 0])), tf32rf(__uint_as_float(r[q * 4 + 1])),
                        tf32rf(__uint_as_float(r[q * 4 + 2])), tf32rf(__uint_as_float(r[q * 4 + 3])));
            } else {
#pragma unroll
                for (int q = 0; q < 8; q++)
                    *(float4*)&cp[q * 4] = make_float4(
                        __uint_as_float(r[q * 4 + 0]), __uint_as_float(r[q * 4 + 1]),
                        __uint_as_float(r[q * 4 + 2]), __uint_as_float(r[q * 4 + 3]));
            }
        }
    }
    __syncthreads();
    if (wid == 0)
        asm volatile("tcgen05.dealloc.cta_group::1.sync.aligned.b32 %0, %1;"
                     :: "r"(tmem), "r"(512u));
#endif  // TC_OK
}

// ===========================================================================
// Path B: mma.sync tf32 GEMM fallback — ALWAYS compiled; runs only when
// g_flag != 0 (tcgen05 output failed the spot check or never ran).
// ===========================================================================
#define MMA_TF32(acc, a0,a1,a2,a3, b0,b1)                                     \
    asm volatile("mma.sync.aligned.m16n8k8.row.col.f32.tf32.tf32.f32 "        \
                 "{%0,%1,%2,%3}, {%4,%5,%6,%7}, {%8,%9}, {%0,%1,%2,%3};"      \
                 : "+f"((acc)[0]), "+f"((acc)[1]), "+f"((acc)[2]), "+f"((acc)[3]) \
                 : "r"(a0), "r"(a1), "r"(a2), "r"(a3), "r"(b0), "r"(b1))

__global__ void __launch_bounds__(256, 2) mma_gemm_nt(
    const float* __restrict__ A, const float* __restrict__ Bw,
    float* __restrict__ C, int M, int N, int K, int round_out)
{
    if (g_flag == 0) return;                     // tcgen05 result verified good

    float* As = (float*)dynraw;                  // [2][128*32]
    float* Bs = (float*)dynraw + 8192;

    const int tid  = threadIdx.x;
    const int lane = tid & 31, w = tid >> 5;
    const int g = lane >> 2, t = lane & 3;
    const int wm = w >> 2, wn = w & 3;
    const int bm = blockIdx.y * 128, bn = blockIdx.x * 128;

    float acc[4][4][4] = {};

    const unsigned sA0 = (unsigned)__cvta_generic_to_shared(As);
    const unsigned sB0 = (unsigned)__cvta_generic_to_shared(Bs);

#define GEMM_STAGE(buf, k0)                                                   \
    {                                                                         \
        unsigned sa = sA0 + (buf) * 16384, sb = sB0 + (buf) * 16384;          \
        _Pragma("unroll")                                                     \
        for (int it = 0; it < 4; it++) {                                      \
            int id = tid + 256 * it;                                          \
            int row = id >> 3, c = id & 7;                                    \
            unsigned off = (unsigned)(row * 32 + ((c ^ (row & 7)) << 2)) * 4; \
            asm volatile("cp.async.ca.shared.global [%0],[%1],16;\n"          \
                         :: "r"(sa + off), "l"(&A [(size_t)(bm + row) * K + (k0) + c * 4])); \
            asm volatile("cp.async.ca.shared.global [%0],[%1],16;\n"          \
                         :: "r"(sb + off), "l"(&Bw[(size_t)(bn + row) * K + (k0) + c * 4])); \
        }                                                                     \
        asm volatile("cp.async.commit_group;\n");                             \
    }

    GEMM_STAGE(0, 0);
    int buf = 0;
    for (int k0 = 0; k0 < K; k0 += 32) {
        asm volatile("cp.async.wait_group 0;\n");
        __syncthreads();
        if (k0 + 32 < K) GEMM_STAGE(buf ^ 1, k0 + 32);

        const float* Ab = As + buf * 4096;
        const float* Bb = Bs + buf * 4096;
#pragma unroll
        for (int o = 0; o < 4; o++) {
            const int c0 = ((2 * o) ^ g) << 2, c1 = ((2 * o + 1) ^ g) << 2;
            unsigned a[4][4], b[4][2];
#pragma unroll
            for (int mt = 0; mt < 4; mt++) {
                int r0 = wm * 64 + mt * 16 + g;
                a[mt][0] = __float_as_uint(Ab[ r0      * 32 + c0 + t]);
                a[mt][2] = __float_as_uint(Ab[ r0      * 32 + c1 + t]);
                a[mt][1] = __float_as_uint(Ab[(r0 + 8) * 32 + c0 + t]);
                a[mt][3] = __float_as_uint(Ab[(r0 + 8) * 32 + c1 + t]);
            }
#pragma unroll
            for (int nt = 0; nt < 4; nt++) {
                int r0 = wn * 32 + nt * 8 + g;
                b[nt][0] = __float_as_uint(Bb[r0 * 32 + c0 + t]);
                b[nt][1] = __float_as_uint(Bb[r0 * 32 + c1 + t]);
            }
#pragma unroll
            for (int mt = 0; mt < 4; mt++)
#pragma unroll
                for (int nt = 0; nt < 4; nt++)
                    MMA_TF32(acc[mt][nt], a[mt][0], a[mt][1], a[mt][2], a[mt][3],
                             b[nt][0], b[nt][1]);
        }
        buf ^= 1;
    }

#pragma unroll
    for (int mt = 0; mt < 4; mt++) {
        int r = bm + wm * 64 + mt * 16 + g;
#pragma unroll
        for (int nt = 0; nt < 4; nt++) {
            int cn = bn + wn * 32 + nt * 8 + 2 * t;
            float v0 = acc[mt][nt][0], v1 = acc[mt][nt][1];
            float v2 = acc[mt][nt][2], v3 = acc[mt][nt][3];
            if (round_out) {
                v0 = tf32rf(v0); v1 = tf32rf(v1); v2 = tf32rf(v2); v3 = tf32rf(v3);
            }
            *(float2*)&C[(size_t)r * N + cn]       = make_float2(v0, v1);
            *(float2*)&C[(size_t)(r + 8) * N + cn] = make_float2(v2, v3);
        }
    }
}

// ---------------------------------------------------------------------------
// RoPE in-place on q,k sections of g_qkv; outputs rounded to tf32.
// ---------------------------------------------------------------------------
__global__ void __launch_bounds__(256) rope_kernel(const int* __restrict__ cu)
{
    int tt = blockIdx.x * 256 + threadIdx.x;
    int j  = tt & 31;
    int hh = (tt >> 5) & 15;
    int s  = (tt >> 9) & 1;
    int r  = tt >> 10;
    if (r >= TOTAL) return;

    int b = 0;
#pragma unroll
    for (int i = 1; i < NB; i++) if (r >= cu[i]) b = i;
    int pos = r - cu[b];

    float inv = exp2f(-(float)j * (13.287712379549449f / 32.0f));
    float fr  = (float)pos * inv;
    float c, sn;
    sincosf(fr, &sn, &c);

    float* base = g_qkv + (size_t)r * NQKV + s * DIMM + hh * HDD;
    float x1 = base[j], x2 = base[j + 32];
    base[j]      = tf32rf(x1 * c - x2 * sn);
    base[j + 32] = tf32rf(x2 * c + x1 * sn);
}

// ---------------------------------------------------------------------------
// Tensor-core flash attention (tf32, mma.sync). g_qkv holds tf32 values so
// staging is pure copies (Q x 0.125 exact). K/V staged via cp.async.
// ---------------------------------------------------------------------------
__global__ void __launch_bounds__(256, 2) attn_kernel(const int* __restrict__ cu)
{
    float* Qs = (float*)dynraw;             // 128*64
    float* Ks = (float*)dynraw + 8192;      // 64*64
    float* Vs = (float*)dynraw + 12288;     // 64*64
    float* Ps = (float*)dynraw + 16384;     // 128*64

    const int tid  = threadIdx.x;
    const int lane = tid & 31, w = tid >> 5;
    const int g = lane >> 2, t = lane & 3;
    const int h  = blockIdx.y;
    const int qt = blockIdx.x * 128;

    const unsigned sK = (unsigned)__cvta_generic_to_shared(Ks);
    const unsigned sV = (unsigned)__cvta_generic_to_shared(Vs);

    int b = 0;
#pragma unroll
    for (int i = 1; i < NB; i++) if (qt >= cu[i]) b = i;
    const int base = cu[b];
    const int L    = cu[b + 1] - base;

#pragma unroll
    for (int it = 0; it < 8; it++) {
        int id = tid + 256 * it;
        int row = id >> 4, c = id & 15;
        float4 v = *(const float4*)&g_qkv[(size_t)(qt + row) * NQKV + h * HDD + c * 4];
        float* d = &Qs[row * 64 + ((c ^ (row & 7)) << 2)];
        d[0] = v.x * 0.125f; d[1] = v.y * 0.125f;
        d[2] = v.z * 0.125f; d[3] = v.w * 0.125f;
    }

    const int r0l = w * 16 + g;
    float m0 = -1e30f, m1 = -1e30f, l0 = 0.f, l1 = 0.f;
    float o_[8][4] = {};

    const int nkt = L >> 6;
    for (int kt = 0; kt < nkt; kt++) {
        __syncthreads();
        const size_t kr0 = (size_t)(base + kt * 64);
#pragma unroll
        for (int it = 0; it < 4; it++) {
            int id = tid + 256 * it;
            int row = id >> 4, c = id & 15;
            const float* src = &g_qkv[(kr0 + row) * NQKV + h * HDD + c * 4];
            unsigned off = (unsigned)(row * 64 + ((c ^ (row & 7)) << 2)) * 4;
            asm volatile("cp.async.ca.shared.global [%0],[%1],16;\n"
                         :: "r"(sK + off), "l"(&src[DIMM]));
            asm volatile("cp.async.ca.shared.global [%0],[%1],16;\n"
                         :: "r"(sV + off), "l"(&src[2 * DIMM]));
        }
        asm volatile("cp.async.commit_group;\n");
        asm volatile("cp.async.wait_group 0;\n");
        __syncthreads();

        float s[8][4] = {};
#pragma unroll
        for (int o = 0; o < 8; o++) {
            const int c0 = ((2 * o) ^ g) << 2, c1 = ((2 * o + 1) ^ g) << 2;
            unsigned a0 = __float_as_uint(Qs[ r0l      * 64 + c0 + t]);
            unsigned a2 = __float_as_uint(Qs[ r0l      * 64 + c1 + t]);
            unsigned a1 = __float_as_uint(Qs[(r0l + 8) * 64 + c0 + t]);
            unsigned a3 = __float_as_uint(Qs[(r0l + 8) * 64 + c1 + t]);
#pragma unroll
            for (int j = 0; j < 8; j++) {
                int rb = j * 8 + g;
                unsigned b0 = __float_as_uint(Ks[rb * 64 + c0 + t]);
                unsigned b1 = __float_as_uint(Ks[rb * 64 + c1 + t]);
                MMA_TF32(s[j], a0, a1, a2, a3, b0, b1);
            }
        }

        float rm0 = -1e30f, rm1 = -1e30f;
#pragma unroll
        for (int j = 0; j < 8; j++) {
            rm0 = fmaxf(rm0, fmaxf(s[j][0], s[j][1]));
            rm1 = fmaxf(rm1, fmaxf(s[j][2], s[j][3]));
        }
#pragma unroll
        for (int off = 1; off < 4; off <<= 1) {
            rm0 = fmaxf(rm0, __shfl_xor_sync(0xffffffffu, rm0, off));
            rm1 = fmaxf(rm1, __shfl_xor_sync(0xffffffffu, rm1, off));
        }
        float mn0 = fmaxf(m0, rm0), mn1 = fmaxf(m1, rm1);
        float f0 = __expf(m0 - mn0), f1 = __expf(m1 - mn1);
        float rs0 = 0.f, rs1 = 0.f;
#pragma unroll
        for (int j = 0; j < 8; j++) {
            s[j][0] = __expf(s[j][0] - mn0); rs0 += s[j][0];
            s[j][1] = __expf(s[j][1] - mn0); rs0 += s[j][1];
            s[j][2] = __expf(s[j][2] - mn1); rs1 += s[j][2];
            s[j][3] = __expf(s[j][3] - mn1); rs1 += s[j][3];
        }
#pragma unroll
        for (int off = 1; off < 4; off <<= 1) {
            rs0 += __shfl_xor_sync(0xffffffffu, rs0, off);
            rs1 += __shfl_xor_sync(0xffffffffu, rs1, off);
        }
        l0 = l0 * f0 + rs0;  m0 = mn0;
        l1 = l1 * f1 + rs1;  m1 = mn1;
#pragma unroll
        for (int j = 0; j < 8; j++) {
            o_[j][0] *= f0; o_[j][1] *= f0;
            o_[j][2] *= f1; o_[j][3] *= f1;
        }

#pragma unroll
        for (int j = 0; j < 8; j++) {
            int ch = 2 * j + (t >> 1);
            int wd = 2 * (t & 1);
            float* p0 = &Ps[ r0l      * 64 + ((ch ^ g) << 2) + wd];
            p0[0] = tf32rf(s[j][0]);
            p0[1] = tf32rf(s[j][1]);
            float* p1 = &Ps[(r0l + 8) * 64 + ((ch ^ g) << 2) + wd];
            p1[0] = tf32rf(s[j][2]);
            p1[1] = tf32rf(s[j][3]);
        }
        __syncwarp();

#pragma unroll
        for (int o = 0; o < 8; o++) {
            const int c0 = ((2 * o) ^ g) << 2, c1 = ((2 * o + 1) ^ g) << 2;
            unsigned a0 = __float_as_uint(Ps[ r0l      * 64 + c0 + t]);
            unsigned a2 = __float_as_uint(Ps[ r0l      * 64 + c1 + t]);
            unsigned a1 = __float_as_uint(Ps[(r0l + 8) * 64 + c0 + t]);
            unsigned a3 = __float_as_uint(Ps[(r0l + 8) * 64 + c1 + t]);
            const int kr  = 8 * o + t;
            const int kr2 = kr + 4;
#pragma unroll
            for (int j = 0; j < 8; j++) {
                int ch = 2 * j + (g >> 2);
                unsigned b0 = __float_as_uint(Vs[kr  * 64 + ((ch ^ (kr  & 7)) << 2) + (g & 3)]);
                unsigned b1 = __float_as_uint(Vs[kr2 * 64 + ((ch ^ (kr2 & 7)) << 2) + (g & 3)]);
                MMA_TF32(o_[j], a0, a1, a2, a3, b0, b1);
            }
        }
        __syncwarp();
    }

    const float npad = (float)(MAXLEN - L);
    float mf0 = (npad > 0.f) ? fmaxf(m0, 0.f) : m0;
    float mf1 = (npad > 0.f) ? fmaxf(m1, 0.f) : m1;
    float sc0 = __expf(m0 - mf0), sc1 = __expf(m1 - mf1);
    float w0 = sc0 / (l0 * sc0 + npad * __expf(-mf0));
    float w1 = sc1 / (l1 * sc1 + npad * __expf(-mf1));

    const int row0 = qt + r0l, row1 = row0 + 8;
#pragma unroll
    for (int j = 0; j < 8; j++) {
        int cn = h * HDD + j * 8 + 2 * t;
        *(float2*)&g_attn[(size_t)row0 * DIMM + cn] = make_float2(
            tf32rf(o_[j][0] * w0), tf32rf(o_[j][1] * w0));
        *(float2*)&g_attn[(size_t)row1 * DIMM + cn] = make_float2(
            tf32rf(o_[j][2] * w1), tf32rf(o_[j][3] * w1));
    }
}

// ---------------------------------------------------------------------------
extern "C" void kernel_launch(void* const* d_in, const int* in_sizes, int n_in,
                              void* d_out, int out_size)
{
    const float* hs   = (const float*)d_in[0];
    const float* wqkv = (const float*)d_in[1];
    const float* wo   = (const float*)d_in[2];
    const int*   cu   = (const int*)  d_in[3];
    float* out = (float*)d_out;

    float *qkv_p, *attn_p, *a_p, *w1_p, *w2_p;
    cudaGetSymbolAddress((void**)&qkv_p,  g_qkv);
    cudaGetSymbolAddress((void**)&attn_p, g_attn);
    cudaGetSymbolAddress((void**)&a_p,    g_a);
    cudaGetSymbolAddress((void**)&w1_p,   g_w1);
    cudaGetSymbolAddress((void**)&w2_p,   g_w2);

    const int tc_smem   = 1024 + 3 * 65536;   // 197632
    const int mma_smem  = 65536;
    const int attn_smem = 98304;
    cudaFuncSetAttribute(tc_gemm_nt,  cudaFuncAttributeMaxDynamicSharedMemorySize, tc_smem);
    cudaFuncSetAttribute(mma_gemm_nt, cudaFuncAttributeMaxDynamicSharedMemorySize, mma_smem);
    cudaFuncSetAttribute(attn_kernel, cudaFuncAttributeMaxDynamicSharedMemorySize, attn_smem);

    // 0) pre-round inputs/weights to tf32 (rna); reset flag
    zero_flag_kernel<<<1, 1>>>();
    cvt_tf32<<<(TOTAL * DIMM / 4 + 255) / 256, 256>>>(hs,   a_p,  TOTAL * DIMM / 4);
    cvt_tf32<<<(NQKV * DIMM / 4 + 255) / 256, 256>>>(wqkv, w1_p, NQKV * DIMM / 4);
    cvt_tf32<<<(DIMM * DIMM / 4 + 255) / 256, 256>>>(wo,   w2_p, DIMM * DIMM / 4);

    // 1) QKV projection: tcgen05 attempt -> spot check -> conditional fallback
    tc_gemm_nt <<<dim3(NQKV / 256, TOTAL / 256), 256, tc_smem >>>(
        a_p, w1_p, qkv_p, TOTAL, NQKV, DIMM, 1);
    check_gemm <<<16, 256>>>(a_p, w1_p, qkv_p, TOTAL, NQKV, DIMM);
    mma_gemm_nt<<<dim3(NQKV / 128, TOTAL / 128), 256, mma_smem>>>(
        a_p, w1_p, qkv_p, TOTAL, NQKV, DIMM, 1);

    // 2) RoPE (rounds q,k to tf32)
    rope_kernel<<<(TOTAL * 2 * NH * 32) / 256, 256>>>(cu);
    // 3) attention
    attn_kernel<<<dim3(TOTAL / 128, NH), 256, attn_smem>>>(cu);

    // 4) output projection (same flag governs fallback)
    tc_gemm_nt <<<dim3(DIMM / 256, TOTAL / 256), 256, tc_smem >>>(
        attn_p, w2_p, out, TOTAL, DIMM, DIMM, 0);
    mma_gemm_nt<<<dim3(DIMM / 128, TOTAL / 128), 256, mma_smem>>>(
        attn_p, w2_p, out, TOTAL, DIMM, DIMM, 0);
}

// round 8
// speedup vs baseline: 3.4192x; 1.0222x over previous
#include <cuda_runtime.h>
#include <math.h>
#include <stdint.h>

#define TOTAL   5120
#define DIMM    1024
#define NH      16
#define HDD     64
#define NB      4
#define MAXLEN  2048
#define NQKV    3072

// tcgen05 only exists on arch-specific/feature sm_103a/sm_100a targets.
#if defined(__CUDA_ARCH__) && (__CUDA_ARCH__ >= 1000) && \
    (defined(__CUDA_ARCH_FEAT_SM103_ALL) || defined(__CUDA_ARCH_FEAT_SM100_ALL))
#define TC_OK 1
#else
#define TC_OK 0
#endif

// Scratch (device globals: no allocation allowed)
__device__ float g_qkv[(size_t)TOTAL * NQKV];    // q|k|v (tf32 values)
__device__ float g_attn[(size_t)TOTAL * DIMM];   // attention out (tf32 values)
__device__ float g_a [(size_t)TOTAL * DIMM];     // hs rounded to tf32
__device__ float g_w1[(size_t)NQKV * DIMM];      // Wqkv rounded to tf32
__device__ float g_w2[(size_t)DIMM * DIMM];      // Wo rounded to tf32
__device__ int   g_flag;                         // 1 => tcgen05 path bad, use fallback

extern __shared__ __align__(1024) uint8_t dynraw[];

__device__ __forceinline__ unsigned tf32r(float x) {
    unsigned u;
    asm("cvt.rna.tf32.f32 %0, %1;" : "=r"(u) : "f"(x));
    return u;
}
__device__ __forceinline__ float tf32rf(float x) {
    return __uint_as_float(tf32r(x));
}

// ---------------------------------------------------------------------------
// Elementwise round-to-tf32 copy (vectorized).
// ---------------------------------------------------------------------------
__global__ void __launch_bounds__(256) cvt_tf32(const float* __restrict__ src,
                                                float* __restrict__ dst, int n4)
{
    int i = blockIdx.x * 256 + threadIdx.x;
    if (i >= n4) return;
    float4 v = ((const float4*)src)[i];
    v.x = tf32rf(v.x); v.y = tf32rf(v.y);
    v.z = tf32rf(v.z); v.w = tf32rf(v.w);
    ((float4*)dst)[i] = v;
}

// ---------------------------------------------------------------------------
// Flag management + GEMM spot-check (4096 sampled dot products).
// ---------------------------------------------------------------------------
__global__ void zero_flag_kernel() { g_flag = 0; }

__global__ void __launch_bounds__(256) check_gemm(
    const float* __restrict__ A, const float* __restrict__ Bw,
    const float* __restrict__ C, int M, int N, int K)
{
    int s = blockIdx.x * 256 + threadIdx.x;      // 4096 samples
    int row = (int)(((unsigned)s * 2654435761u) % (unsigned)M);
    int col = (int)(((unsigned)s * 40503u + 17u) % (unsigned)N);
    const float* a = &A[(size_t)row * K];
    const float* b = &Bw[(size_t)col * K];
    float ref = 0.f;
    for (int k = 0; k < K; k += 4) {
        float4 av = *(const float4*)&a[k];
        float4 bv = *(const float4*)&b[k];
        ref += av.x * bv.x + av.y * bv.y + av.z * bv.z + av.w * bv.w;
    }
    float got = C[(size_t)row * N + col];
    if (fabsf(got - ref) > 1e-2f * (1.0f + fabsf(ref)))
        atomicOr(&g_flag, 1);
}

// ===========================================================================
// Path A: tcgen05 GEMM (body only on sm_103a/sm_100a feature targets).
// 256x256 CTA tile, K=32 per buffer, DOUBLE-buffered GENERIC staging
// (LDG -> regs -> st.shared.v4, exactly the mechanism of the verified
// SS-MMA example), per-thread fence.proxy.async + __syncthreads before
// each MMA issue. TMEM D (512 cols). Two M=128 x N=256 MMAs per K8-step.
// Dynamic smem: [0:16) two mbarriers, [16:20) tmem ptr, [1024:...) tiles.
// ===========================================================================
__global__ void __launch_bounds__(256, 1) tc_gemm_nt(
    const float* __restrict__ A, const float* __restrict__ Bw,
    float* __restrict__ C, int M, int N, int K, int round_out)
{
#if TC_OK
    const int tid = threadIdx.x;
    const int wid = tid >> 5;
    const int bm = blockIdx.y * 256, bn = blockIdx.x * 256;

    const uint32_t sbase = (uint32_t)__cvta_generic_to_shared(dynraw);
    const uint32_t mbar0 = sbase;
    const uint32_t tptr  = sbase + 16;
    const uint32_t tile0 = sbase + 1024;

    if (wid == 0) {
        asm volatile("tcgen05.alloc.cta_group::1.sync.aligned.shared::cta.b32 [%0], %1;"
                     :: "r"(tptr), "r"(512u) : "memory");
        asm volatile("tcgen05.relinquish_alloc_permit.cta_group::1.sync.aligned;");
    }
    if (tid == 0) {
        asm volatile("mbarrier.init.shared.b64 [%0], 1;" :: "r"(mbar0) : "memory");
        asm volatile("mbarrier.init.shared.b64 [%0], 1;" :: "r"(mbar0 + 8) : "memory");
    }
    __syncthreads();
    uint32_t tmem;
    asm volatile("ld.shared.b32 %0, [%1];" : "=r"(tmem) : "r"(tptr));

    const uint64_t desc_base = (uint64_t(2) << 61) | (uint64_t(1) << 46)
                             | (uint64_t(64) << 32) | (uint64_t(1) << 16);
    const uint32_t idesc = (1u << 4) | (2u << 7) | (2u << 10)
                         | ((256u / 8) << 17) | ((128u / 16) << 24);

    const int T = K >> 5;
    const int row8 = tid >> 3, c8 = tid & 7;     // each thread: 8 (row,c) pairs
    float4 ra[8], rb[8];

#define TC_LDG(j)                                                             \
    {                                                                         \
        int k0 = (j) << 5;                                                    \
        _Pragma("unroll")                                                     \
        for (int it = 0; it < 8; it++) {                                      \
            int row = row8 + 32 * it;                                         \
            ra[it] = *(const float4*)&A [(size_t)(bm + row) * K + k0 + c8 * 4]; \
            rb[it] = *(const float4*)&Bw[(size_t)(bn + row) * K + k0 + c8 * 4]; \
        }                                                                     \
    }
#define TC_STS(b)                                                             \
    {                                                                         \
        uint32_t buf = tile0 + (b) * 65536u;                                  \
        _Pragma("unroll")                                                     \
        for (int it = 0; it < 8; it++) {                                      \
            int row = row8 + 32 * it;                                         \
            uint32_t off = buf + (uint32_t)(row * 128 + ((c8 ^ (row & 7)) << 4)); \
            asm volatile("st.shared.v4.b32 [%0],{%1,%2,%3,%4};"               \
                :: "r"(off), "r"(__float_as_uint(ra[it].x)),                  \
                   "r"(__float_as_uint(ra[it].y)), "r"(__float_as_uint(ra[it].z)), \
                   "r"(__float_as_uint(ra[it].w)) : "memory");                \
            asm volatile("st.shared.v4.b32 [%0],{%1,%2,%3,%4};"               \
                :: "r"(off + 32768u), "r"(__float_as_uint(rb[it].x)),         \
                   "r"(__float_as_uint(rb[it].y)), "r"(__float_as_uint(rb[it].z)), \
                   "r"(__float_as_uint(rb[it].w)) : "memory");                \
        }                                                                     \
    }
#define TC_MWAIT(j)                                                           \
    {                                                                         \
        uint32_t ad = mbar0 + (((j) & 1) << 3);                               \
        uint32_t pr = ((j) >> 1) & 1;                                         \
        asm volatile("{\n\t.reg .pred P1;\n\t"                                \
                     "W_%=:\n\t"                                              \
                     "mbarrier.try_wait.parity.acquire.cta.shared::cta.b64 P1, [%0], %1, 0x989680;\n\t" \
                     "@P1 bra.uni D_%=;\n\t"                                  \
                     "bra.uni W_%=;\n\t"                                      \
                     "D_%=:\n\t}" :: "r"(ad), "r"(pr) : "memory");            \
    }

    TC_LDG(0);
    TC_STS(0);
    asm volatile("fence.proxy.async.shared::cta;" ::: "memory");
    __syncthreads();

    for (int i = 0; i < T; i++) {
        // ---- issue MMAs on buffer i&1 (visible: fence+sync last iter) ----
        if (wid == 0) {
            uint32_t one;
            asm volatile("{\n\t.reg .pred p;\n\telect.sync _|p, 0xFFFFFFFF;\n\t"
                         "selp.b32 %0, 1, 0, p;\n\t}" : "=r"(one));
            if (one) {
                uint32_t buf = tile0 + (uint32_t)(i & 1) * 65536u;
                uint64_t ad = desc_base | ((uint64_t)(buf >> 4) & 0x3FFF);
                uint64_t bd = desc_base | ((uint64_t)((buf + 32768u) >> 4) & 0x3FFF);
#pragma unroll
                for (int ks = 0; ks < 4; ks++) {
                    uint32_t en = (i > 0) || (ks > 0);
                    asm volatile("{\n\t.reg .pred p;\n\tsetp.ne.u32 p, %4, 0;\n\t"
                                 "tcgen05.mma.cta_group::1.kind::tf32 [%0], %1, %2, %3, {%5,%5,%5,%5}, p;\n\t}"
                                 :: "r"(tmem), "l"(ad + ks * 2), "l"(bd + ks * 2),
                                    "r"(idesc), "r"(en), "r"(0u) : "memory");
                    asm volatile("{\n\t.reg .pred p;\n\tsetp.ne.u32 p, %4, 0;\n\t"
                                 "tcgen05.mma.cta_group::1.kind::tf32 [%0], %1, %2, %3, {%5,%5,%5,%5}, p;\n\t}"
                                 :: "r"(tmem + 256), "l"(ad + 1024 + ks * 2), "l"(bd + ks * 2),
                                    "r"(idesc), "r"(en), "r"(0u) : "memory");
                }
                asm volatile("tcgen05.commit.cta_group::1.mbarrier::arrive::one.shared::cluster.b64 [%0];"
                             :: "r"(mbar0 + ((i & 1) << 3)) : "memory");
            }
        }
        // ---- stage tile i+1 into the other buffer (overlaps MMA i) ----
        if (i + 1 < T) {
            TC_LDG(i + 1);
            if (i >= 1) TC_MWAIT(i - 1);         // MMA i-1 done => its buffer free
            TC_STS((i + 1) & 1);
        }
        asm volatile("fence.proxy.async.shared::cta;" ::: "memory");
        __syncthreads();
    }
    TC_MWAIT(T - 1);
    asm volatile("tcgen05.fence::after_thread_sync;" ::: "memory");

    // ---- epilogue: warps 0-3 read M-half 0 (cols 0-255), 4-7 half 1 ----
    {
        const int w4 = wid & 3, half = wid >> 2;
        const uint32_t warp_off = ((uint32_t)w4) << 21;
        const uint32_t col0 = half * 256;
        const int grow = bm + half * 128 + w4 * 32 + (tid & 31);
#pragma unroll
        for (int ch = 0; ch < 8; ch++) {
            uint32_t r[32];
            asm volatile("tcgen05.ld.sync.aligned.32x32b.x32.b32 "
                "{%0, %1, %2, %3, %4, %5, %6, %7, "
                " %8, %9, %10, %11, %12, %13, %14, %15, "
                " %16, %17, %18, %19, %20, %21, %22, %23, "
                " %24, %25, %26, %27, %28, %29, %30, %31}, [%32];"
                : "=r"(r[0]),  "=r"(r[1]),  "=r"(r[2]),  "=r"(r[3]),
                  "=r"(r[4]),  "=r"(r[5]),  "=r"(r[6]),  "=r"(r[7]),
                  "=r"(r[8]),  "=r"(r[9]),  "=r"(r[10]), "=r"(r[11]),
                  "=r"(r[12]), "=r"(r[13]), "=r"(r[14]), "=r"(r[15]),
                  "=r"(r[16]), "=r"(r[17]), "=r"(r[18]), "=r"(r[19]),
                  "=r"(r[20]), "=r"(r[21]), "=r"(r[22]), "=r"(r[23]),
                  "=r"(r[24]), "=r"(r[25]), "=r"(r[26]), "=r"(r[27]),
                  "=r"(r[28]), "=r"(r[29]), "=r"(r[30]), "=r"(r[31])
                : "r"(tmem + warp_off + col0 + ch * 32));
            asm volatile("tcgen05.wait::ld.sync.aligned;" ::: "memory");
            float* cp = &C[(size_t)grow * N + bn + ch * 32];
            if (round_out) {
#pragma unroll
                for (int q = 0; q < 8; q++)
                    *(float4*)&cp[q * 4] = make_float4(
                        tf32rf(__uint_as_float(r[q * 4 + 0])), tf32rf(__uint_as_float(r[q * 4 + 1])),
                        tf32rf(__uint_as_float(r[q * 4 + 2])), tf32rf(__uint_as_float(r[q * 4 + 3])));
            } else {
#pragma unroll
                for (int q = 0; q < 8; q++)
                    *(float4*)&cp[q * 4] = make_float4(
                        __uint_as_float(r[q * 4 + 0]), __uint_as_float(r[q * 4 + 1]),
                        __uint_as_float(r[q * 4 + 2]), __uint_as_float(r[q * 4 + 3]));
            }
        }
    }
    __syncthreads();
    if (wid == 0)
        asm volatile("tcgen05.dealloc.cta_group::1.sync.aligned.b32 %0, %1;"
                     :: "r"(tmem), "r"(512u));
#endif  // TC_OK
}

// ===========================================================================
// Path B: mma.sync tf32 GEMM fallback — ALWAYS compiled; runs only when
// g_flag != 0 (tcgen05 output failed the spot check or never ran).
// ===========================================================================
#define MMA_TF32(acc, a0,a1,a2,a3, b0,b1)                                     \
    asm volatile("mma.sync.aligned.m16n8k8.row.col.f32.tf32.tf32.f32 "        \
                 "{%0,%1,%2,%3}, {%4,%5,%6,%7}, {%8,%9}, {%0,%1,%2,%3};"      \
                 : "+f"((acc)[0]), "+f"((acc)[1]), "+f"((acc)[2]), "+f"((acc)[3]) \
                 : "r"(a0), "r"(a1), "r"(a2), "r"(a3), "r"(b0), "r"(b1))

__global__ void __launch_bounds__(256, 2) mma_gemm_nt(
    const float* __restrict__ A, const float* __restrict__ Bw,
    float* __restrict__ C, int M, int N, int K, int round_out)
{
    if (g_flag == 0) return;                     // tcgen05 result verified good

    float* As = (float*)dynraw;                  // [2][128*32]
    float* Bs = (float*)dynraw + 8192;

    const int tid  = threadIdx.x;
    const int lane = tid & 31, w = tid >> 5;
    const int g = lane >> 2, t = lane & 3;
    const int wm = w >> 2, wn = w & 3;
    const int bm = blockIdx.y * 128, bn = blockIdx.x * 128;

    float acc[4][4][4] = {};

    const unsigned sA0 = (unsigned)__cvta_generic_to_shared(As);
    const unsigned sB0 = (unsigned)__cvta_generic_to_shared(Bs);

#define GEMM_STAGE(buf, k0)                                                   \
    {                                                                         \
        unsigned sa = sA0 + (buf) * 16384, sb = sB0 + (buf) * 16384;          \
        _Pragma("unroll")                                                     \
        for (int it = 0; it < 4; it++) {                                      \
            int id = tid + 256 * it;                                          \
            int row = id >> 3, c = id & 7;                                    \
            unsigned off = (unsigned)(row * 32 + ((c ^ (row & 7)) << 2)) * 4; \
            asm volatile("cp.async.ca.shared.global [%0],[%1],16;\n"          \
                         :: "r"(sa + off), "l"(&A [(size_t)(bm + row) * K + (k0) + c * 4])); \
            asm volatile("cp.async.ca.shared.global [%0],[%1],16;\n"          \
                         :: "r"(sb + off), "l"(&Bw[(size_t)(bn + row) * K + (k0) + c * 4])); \
        }                                                                     \
        asm volatile("cp.async.commit_group;\n");                             \
    }

    GEMM_STAGE(0, 0);
    int buf = 0;
    for (int k0 = 0; k0 < K; k0 += 32) {
        asm volatile("cp.async.wait_group 0;\n");
        __syncthreads();
        if (k0 + 32 < K) GEMM_STAGE(buf ^ 1, k0 + 32);

        const float* Ab = As + buf * 4096;
        const float* Bb = Bs + buf * 4096;
#pragma unroll
        for (int o = 0; o < 4; o++) {
            const int c0 = ((2 * o) ^ g) << 2, c1 = ((2 * o + 1) ^ g) << 2;
            unsigned a[4][4], b[4][2];
#pragma unroll
            for (int mt = 0; mt < 4; mt++) {
                int r0 = wm * 64 + mt * 16 + g;
                a[mt][0] = __float_as_uint(Ab[ r0      * 32 + c0 + t]);
                a[mt][2] = __float_as_uint(Ab[ r0      * 32 + c1 + t]);
                a[mt][1] = __float_as_uint(Ab[(r0 + 8) * 32 + c0 + t]);
                a[mt][3] = __float_as_uint(Ab[(r0 + 8) * 32 + c1 + t]);
            }
#pragma unroll
            for (int nt = 0; nt < 4; nt++) {
                int r0 = wn * 32 + nt * 8 + g;
                b[nt][0] = __float_as_uint(Bb[r0 * 32 + c0 + t]);
                b[nt][1] = __float_as_uint(Bb[r0 * 32 + c1 + t]);
            }
#pragma unroll
            for (int mt = 0; mt < 4; mt++)
#pragma unroll
                for (int nt = 0; nt < 4; nt++)
                    MMA_TF32(acc[mt][nt], a[mt][0], a[mt][1], a[mt][2], a[mt][3],
                             b[nt][0], b[nt][1]);
        }
        buf ^= 1;
    }

#pragma unroll
    for (int mt = 0; mt < 4; mt++) {
        int r = bm + wm * 64 + mt * 16 + g;
#pragma unroll
        for (int nt = 0; nt < 4; nt++) {
            int cn = bn + wn * 32 + nt * 8 + 2 * t;
            float v0 = acc[mt][nt][0], v1 = acc[mt][nt][1];
            float v2 = acc[mt][nt][2], v3 = acc[mt][nt][3];
            if (round_out) {
                v0 = tf32rf(v0); v1 = tf32rf(v1); v2 = tf32rf(v2); v3 = tf32rf(v3);
            }
            *(float2*)&C[(size_t)r * N + cn]       = make_float2(v0, v1);
            *(float2*)&C[(size_t)(r + 8) * N + cn] = make_float2(v2, v3);
        }
    }
}

// ---------------------------------------------------------------------------
// RoPE in-place on q,k sections of g_qkv; outputs rounded to tf32.
// ---------------------------------------------------------------------------
__global__ void __launch_bounds__(256) rope_kernel(const int* __restrict__ cu)
{
    int tt = blockIdx.x * 256 + threadIdx.x;
    int j  = tt & 31;
    int hh = (tt >> 5) & 15;
    int s  = (tt >> 9) & 1;
    int r  = tt >> 10;
    if (r >= TOTAL) return;

    int b = 0;
#pragma unroll
    for (int i = 1; i < NB; i++) if (r >= cu[i]) b = i;
    int pos = r - cu[b];

    float inv = exp2f(-(float)j * (13.287712379549449f / 32.0f));
    float fr  = (float)pos * inv;
    float c, sn;
    sincosf(fr, &sn, &c);

    float* base = g_qkv + (size_t)r * NQKV + s * DIMM + hh * HDD;
    float x1 = base[j], x2 = base[j + 32];
    base[j]      = tf32rf(x1 * c - x2 * sn);
    base[j + 32] = tf32rf(x2 * c + x1 * sn);
}

// ---------------------------------------------------------------------------
// Tensor-core flash attention (tf32, mma.sync). g_qkv holds tf32 values so
// staging is pure copies (Q x 0.125 exact). K/V staged via cp.async.
// ---------------------------------------------------------------------------
__global__ void __launch_bounds__(256, 2) attn_kernel(const int* __restrict__ cu)
{
    float* Qs = (float*)dynraw;             // 128*64
    float* Ks = (float*)dynraw + 8192;      // 64*64
    float* Vs = (float*)dynraw + 12288;     // 64*64
    float* Ps = (float*)dynraw + 16384;     // 128*64

    const int tid  = threadIdx.x;
    const int lane = tid & 31, w = tid >> 5;
    const int g = lane >> 2, t = lane & 3;
    const int h  = blockIdx.y;
    const int qt = blockIdx.x * 128;

    const unsigned sK = (unsigned)__cvta_generic_to_shared(Ks);
    const unsigned sV = (unsigned)__cvta_generic_to_shared(Vs);

    int b = 0;
#pragma unroll
    for (int i = 1; i < NB; i++) if (qt >= cu[i]) b = i;
    const int base = cu[b];
    const int L    = cu[b + 1] - base;

#pragma unroll
    for (int it = 0; it < 8; it++) {
        int id = tid + 256 * it;
        int row = id >> 4, c = id & 15;
        float4 v = *(const float4*)&g_qkv[(size_t)(qt + row) * NQKV + h * HDD + c * 4];
        float* d = &Qs[row * 64 + ((c ^ (row & 7)) << 2)];
        d[0] = v.x * 0.125f; d[1] = v.y * 0.125f;
        d[2] = v.z * 0.125f; d[3] = v.w * 0.125f;
    }

    const int r0l = w * 16 + g;
    float m0 = -1e30f, m1 = -1e30f, l0 = 0.f, l1 = 0.f;
    float o_[8][4] = {};

    const int nkt = L >> 6;
    for (int kt = 0; kt < nkt; kt++) {
        __syncthreads();
        const size_t kr0 = (size_t)(base + kt * 64);
#pragma unroll
        for (int it = 0; it < 4; it++) {
            int id = tid + 256 * it;
            int row = id >> 4, c = id & 15;
            const float* src = &g_qkv[(kr0 + row) * NQKV + h * HDD + c * 4];
            unsigned off = (unsigned)(row * 64 + ((c ^ (row & 7)) << 2)) * 4;
            asm volatile("cp.async.ca.shared.global [%0],[%1],16;\n"
                         :: "r"(sK + off), "l"(&src[DIMM]));
            asm volatile("cp.async.ca.shared.global [%0],[%1],16;\n"
                         :: "r"(sV + off), "l"(&src[2 * DIMM]));
        }
        asm volatile("cp.async.commit_group;\n");
        asm volatile("cp.async.wait_group 0;\n");
        __syncthreads();

        float s[8][4] = {};
#pragma unroll
        for (int o = 0; o < 8; o++) {
            const int c0 = ((2 * o) ^ g) << 2, c1 = ((2 * o + 1) ^ g) << 2;
            unsigned a0 = __float_as_uint(Qs[ r0l      * 64 + c0 + t]);
            unsigned a2 = __float_as_uint(Qs[ r0l      * 64 + c1 + t]);
            unsigned a1 = __float_as_uint(Qs[(r0l + 8) * 64 + c0 + t]);
            unsigned a3 = __float_as_uint(Qs[(r0l + 8) * 64 + c1 + t]);
#pragma unroll
            for (int j = 0; j < 8; j++) {
                int rb = j * 8 + g;
                unsigned b0 = __float_as_uint(Ks[rb * 64 + c0 + t]);
                unsigned b1 = __float_as_uint(Ks[rb * 64 + c1 + t]);
                MMA_TF32(s[j], a0, a1, a2, a3, b0, b1);
            }
        }

        float rm0 = -1e30f, rm1 = -1e30f;
#pragma unroll
        for (int j = 0; j < 8; j++) {
            rm0 = fmaxf(rm0, fmaxf(s[j][0], s[j][1]));
            rm1 = fmaxf(rm1, fmaxf(s[j][2], s[j][3]));
        }
#pragma unroll
        for (int off = 1; off < 4; off <<= 1) {
            rm0 = fmaxf(rm0, __shfl_xor_sync(0xffffffffu, rm0, off));
            rm1 = fmaxf(rm1, __shfl_xor_sync(0xffffffffu, rm1, off));
        }
        float mn0 = fmaxf(m0, rm0), mn1 = fmaxf(m1, rm1);
        float f0 = __expf(m0 - mn0), f1 = __expf(m1 - mn1);
        float rs0 = 0.f, rs1 = 0.f;
#pragma unroll
        for (int j = 0; j < 8; j++) {
            s[j][0] = __expf(s[j][0] - mn0); rs0 += s[j][0];
            s[j][1] = __expf(s[j][1] - mn0); rs0 += s[j][1];
            s[j][2] = __expf(s[j][2] - mn1); rs1 += s[j][2];
            s[j][3] = __expf(s[j][3] - mn1); rs1 += s[j][3];
        }
#pragma unroll
        for (int off = 1; off < 4; off <<= 1) {
            rs0 += __shfl_xor_sync(0xffffffffu, rs0, off);
            rs1 += __shfl_xor_sync(0xffffffffu, rs1, off);
        }
        l0 = l0 * f0 + rs0;  m0 = mn0;
        l1 = l1 * f1 + rs1;  m1 = mn1;
#pragma unroll
        for (int j = 0; j < 8; j++) {
            o_[j][0] *= f0; o_[j][1] *= f0;
            o_[j][2] *= f1; o_[j][3] *= f1;
        }

#pragma unroll
        for (int j = 0; j < 8; j++) {
            int ch = 2 * j + (t >> 1);
            int wd = 2 * (t & 1);
            float* p0 = &Ps[ r0l      * 64 + ((ch ^ g) << 2) + wd];
            p0[0] = tf32rf(s[j][0]);
            p0[1] = tf32rf(s[j][1]);
            float* p1 = &Ps[(r0l + 8) * 64 + ((ch ^ g) << 2) + wd];
            p1[0] = tf32rf(s[j][2]);
            p1[1] = tf32rf(s[j][3]);
        }
        __syncwarp();

#pragma unroll
        for (int o = 0; o < 8; o++) {
            const int c0 = ((2 * o) ^ g) << 2, c1 = ((2 * o + 1) ^ g) << 2;
            unsigned a0 = __float_as_uint(Ps[ r0l      * 64 + c0 + t]);
            unsigned a2 = __float_as_uint(Ps[ r0l      * 64 + c1 + t]);
            unsigned a1 = __float_as_uint(Ps[(r0l + 8) * 64 + c0 + t]);
            unsigned a3 = __float_as_uint(Ps[(r0l + 8) * 64 + c1 + t]);
            const int kr  = 8 * o + t;
            const int kr2 = kr + 4;
#pragma unroll
            for (int j = 0; j < 8; j++) {
                int ch = 2 * j + (g >> 2);
                unsigned b0 = __float_as_uint(Vs[kr  * 64 + ((ch ^ (kr  & 7)) << 2) + (g & 3)]);
                unsigned b1 = __float_as_uint(Vs[kr2 * 64 + ((ch ^ (kr2 & 7)) << 2) + (g & 3)]);
                MMA_TF32(o_[j], a0, a1, a2, a3, b0, b1);
            }
        }
        __syncwarp();
    }

    const float npad = (float)(MAXLEN - L);
    float mf0 = (npad > 0.f) ? fmaxf(m0, 0.f) : m0;
    float mf1 = (npad > 0.f) ? fmaxf(m1, 0.f) : m1;
    float sc0 = __expf(m0 - mf0), sc1 = __expf(m1 - mf1);
    float w0 = sc0 / (l0 * sc0 + npad * __expf(-mf0));
    float w1 = sc1 / (l1 * sc1 + npad * __expf(-mf1));

    const int row0 = qt + r0l, row1 = row0 + 8;
#pragma unroll
    for (int j = 0; j < 8; j++) {
        int cn = h * HDD + j * 8 + 2 * t;
        *(float2*)&g_attn[(size_t)row0 * DIMM + cn] = make_float2(
            tf32rf(o_[j][0] * w0), tf32rf(o_[j][1] * w0));
        *(float2*)&g_attn[(size_t)row1 * DIMM + cn] = make_float2(
            tf32rf(o_[j][2] * w1), tf32rf(o_[j][3] * w1));
    }
}

// ---------------------------------------------------------------------------
extern "C" void kernel_launch(void* const* d_in, const int* in_sizes, int n_in,
                              void* d_out, int out_size)
{
    const float* hs   = (const float*)d_in[0];
    const float* wqkv = (const float*)d_in[1];
    const float* wo   = (const float*)d_in[2];
    const int*   cu   = (const int*)  d_in[3];
    float* out = (float*)d_out;

    float *qkv_p, *attn_p, *a_p, *w1_p, *w2_p;
    cudaGetSymbolAddress((void**)&qkv_p,  g_qkv);
    cudaGetSymbolAddress((void**)&attn_p, g_attn);
    cudaGetSymbolAddress((void**)&a_p,    g_a);
    cudaGetSymbolAddress((void**)&w1_p,   g_w1);
    cudaGetSymbolAddress((void**)&w2_p,   g_w2);

    const int tc_smem   = 1024 + 2 * 65536;   // 132096 (double-buffered)
    const int mma_smem  = 65536;
    const int attn_smem = 98304;
    cudaFuncSetAttribute(tc_gemm_nt,  cudaFuncAttributeMaxDynamicSharedMemorySize, tc_smem);
    cudaFuncSetAttribute(mma_gemm_nt, cudaFuncAttributeMaxDynamicSharedMemorySize, mma_smem);
    cudaFuncSetAttribute(attn_kernel, cudaFuncAttributeMaxDynamicSharedMemorySize, attn_smem);

    // 0) pre-round inputs/weights to tf32 (rna); reset flag
    zero_flag_kernel<<<1, 1>>>();
    cvt_tf32<<<(TOTAL * DIMM / 4 + 255) / 256, 256>>>(hs,   a_p,  TOTAL * DIMM / 4);
    cvt_tf32<<<(NQKV * DIMM / 4 + 255) / 256, 256>>>(wqkv, w1_p, NQKV * DIMM / 4);
    cvt_tf32<<<(DIMM * DIMM / 4 + 255) / 256, 256>>>(wo,   w2_p, DIMM * DIMM / 4);

    // 1) QKV projection: tcgen05 attempt -> spot check -> conditional fallback
    tc_gemm_nt <<<dim3(NQKV / 256, TOTAL / 256), 256, tc_smem >>>(
        a_p, w1_p, qkv_p, TOTAL, NQKV, DIMM, 1);
    check_gemm <<<16, 256>>>(a_p, w1_p, qkv_p, TOTAL, NQKV, DIMM);
    mma_gemm_nt<<<dim3(NQKV / 128, TOTAL / 128), 256, mma_smem>>>(
        a_p, w1_p, qkv_p, TOTAL, NQKV, DIMM, 1);

    // 2) RoPE (rounds q,k to tf32)
    rope_kernel<<<(TOTAL * 2 * NH * 32) / 256, 256>>>(cu);
    // 3) attention
    attn_kernel<<<dim3(TOTAL / 128, NH), 256, attn_smem>>>(cu);

    // 4) output projection (same flag governs fallback)
    tc_gemm_nt <<<dim3(DIMM / 256, TOTAL / 256), 256, tc_smem >>>(
        attn_p, w2_p, out, TOTAL, DIMM, DIMM, 0);
    mma_gemm_nt<<<dim3(DIMM / 128, TOTAL / 128), 256, mma_smem>>>(
        attn_p, w2_p, out, TOTAL, DIMM, DIMM, 0);
}